// round 10
// baseline (speedup 1.0000x reference)
#include <cuda_runtime.h>
#include <cuda_fp16.h>
#include <cstdint>

#define NN 20000
#define NE 160000

// ---------------- scratch (device globals: allocation-free) ----------------
__device__ __half g_xhi[NN * 128], g_xlo[NN * 128];
__device__ float g_xlr1[NN * 256];
__device__ __half g_h1hi[NN * 128], g_h1lo[NN * 128];
__device__ float g_xlr2[NN * 1024];
__device__ __half g_h2hi[NN * 512], g_h2lo[NN * 512];
__device__ __half g_wt1h[256 * 128];
__device__ __half g_wt2h[1024 * 128];
__device__ __half g_wtlh[64 * 512];
__device__ float g_cb1[256];
__device__ float g_cb2[1024];
__device__ int g_deg[NN];
__device__ int g_rowptr[NN + 1];
__device__ int g_cursor[NN];
__device__ int g_col[NE];

// ---------------- helpers ----------------
__device__ __forceinline__ uint32_t smem_u32(const void* p) {
    uint32_t a;
    asm("{ .reg .u64 t; cvta.to.shared.u64 t, %1; cvt.u32.u64 %0, t; }" : "=r"(a) : "l"(p));
    return a;
}
__device__ __forceinline__ void cp_async16(uint32_t dst, const void* src, bool pred) {
    int sz = pred ? 16 : 0;
    asm volatile("cp.async.cg.shared.global [%0], [%1], 16, %2;"
                 :: "r"(dst), "l"(src), "r"(sz) : "memory");
}
__device__ __forceinline__ void cp_commit() {
    asm volatile("cp.async.commit_group;" ::: "memory");
}
template <int W> __device__ __forceinline__ void cp_wait() {
    asm volatile("cp.async.wait_group %0;" :: "n"(W) : "memory");
}
__device__ __forceinline__ void split1h(float a, __half& h, __half& l) {
    h = __float2half_rn(a);
    l = __float2half_rn(a - __half2float(h));
}
__device__ __forceinline__ void mma_f16(float* c, const uint32_t* a, const uint32_t* b) {
    asm volatile("mma.sync.aligned.m16n8k16.row.col.f32.f16.f16.f32 "
                 "{%0,%1,%2,%3}, {%4,%5,%6,%7}, {%8,%9}, {%0,%1,%2,%3};"
                 : "+f"(c[0]), "+f"(c[1]), "+f"(c[2]), "+f"(c[3])
                 : "r"(a[0]), "r"(a[1]), "r"(a[2]), "r"(a[3]), "r"(b[0]), "r"(b[1]));
}
__device__ __forceinline__ void ldsm_x4(uint32_t* r, uint32_t addr) {
    asm volatile("ldmatrix.sync.aligned.m8n8.x4.shared.b16 {%0,%1,%2,%3}, [%4];"
                 : "=r"(r[0]), "=r"(r[1]), "=r"(r[2]), "=r"(r[3]) : "r"(addr));
}

// ---------------- fused prep: zero_deg + x split + W transposes + bias -----
__global__ void k_prep(const float* __restrict__ x,
                       const float* __restrict__ Wl1, const float* __restrict__ Wr1,
                       const float* __restrict__ Wl2, const float* __restrict__ Wr2,
                       const float* __restrict__ Wlin,
                       const float* __restrict__ bl1, const float* __restrict__ br1,
                       const float* __restrict__ bl2, const float* __restrict__ br2) {
    const int S0 = NN;
    const int S1 = S0 + NN * 128;
    const int S2 = S1 + 16384;
    const int S3 = S2 + 16384;
    const int S4 = S3 + 65536;
    const int S5 = S4 + 65536;
    const int S6 = S5 + 32768;
    const int S7 = S6 + 1280;
    int i = blockIdx.x * blockDim.x + threadIdx.x;
    if (i < S0) {
        g_deg[i] = 0;
    } else if (i < S1) {
        int j = i - S0;
        __half h, l;
        split1h(x[j], h, l);
        g_xhi[j] = h; g_xlo[j] = l;
    } else if (i < S2) {
        int j = i - S1, k = j >> 7, n = j & 127;
        g_wt1h[n * 128 + k] = __float2half_rn(Wl1[j]);
    } else if (i < S3) {
        int j = i - S2, k = j >> 7, n = j & 127;
        g_wt1h[128 * 128 + n * 128 + k] = __float2half_rn(Wr1[j]);
    } else if (i < S4) {
        int j = i - S3, k = j >> 9, n = j & 511;
        g_wt2h[n * 128 + k] = __float2half_rn(Wl2[j]);
    } else if (i < S5) {
        int j = i - S4, k = j >> 9, n = j & 511;
        g_wt2h[512 * 128 + n * 128 + k] = __float2half_rn(Wr2[j]);
    } else if (i < S6) {
        int j = i - S5, k = j >> 6, n = j & 63;
        g_wtlh[n * 512 + k] = __float2half_rn(Wlin[j]);
    } else if (i < S7) {
        int j = i - S6;
        if (j < 256) g_cb1[j] = (j < 128) ? bl1[j] : br1[j - 128];
        else {
            int b = j - 256;
            g_cb2[b] = (b < 512) ? bl2[b] : br2[b - 512];
        }
    }
}
#define PREP_TOTAL (NN + NN * 128 + 16384 * 2 + 65536 * 2 + 32768 + 1280)

// ---------------- CSR build (counting sort by dst) ----------------
__global__ void k_hist(const int* __restrict__ dst) {
    int e = blockIdx.x * blockDim.x + threadIdx.x;
    if (e < NE) atomicAdd(&g_deg[dst[e]], 1);
}
__global__ void k_scan() {
    __shared__ int s[1024];
    const int CH = (NN + 1023) / 1024;
    int t = threadIdx.x;
    int start = t * CH;
    int end = start + CH < NN ? start + CH : NN;
    int sum = 0;
    for (int i = start; i < end; i++) sum += g_deg[i];
    s[t] = sum;
    __syncthreads();
    for (int off = 1; off < 1024; off <<= 1) {
        int v = (t >= off) ? s[t - off] : 0;
        __syncthreads();
        s[t] += v;
        __syncthreads();
    }
    int run = (t == 0) ? 0 : s[t - 1];
    for (int i = start; i < end; i++) {
        g_rowptr[i] = run;
        g_cursor[i] = run;
        run += g_deg[i];
    }
    if (t == 1023) g_rowptr[NN] = s[1023];
}
__global__ void k_scatter(const int* __restrict__ src, const int* __restrict__ dst) {
    int e = blockIdx.x * blockDim.x + threadIdx.x;
    if (e < NE) {
        int d = dst[e];
        int pos = atomicAdd(&g_cursor[d], 1);
        g_col[pos] = src[e];
    }
}

// ---------------- pipelined fp16 2-MMA split GEMM (frozen from R9) --------
template <int BN>
__global__ void __launch_bounds__(256, 3)
gemm_f16(const __half* __restrict__ Ahi, const __half* __restrict__ Alo,
         const __half* __restrict__ Bh, const float* __restrict__ bias,
         float* __restrict__ C, int M, int N, int K) {
    constexpr int BM = 64;
    constexpr int BK = 32;
    constexpr int STR = 40;
    constexpr int ASZ = BM * STR;
    constexpr int BSZ = BN * STR;
    constexpr int STAGE = 2 * ASZ + BSZ;
    constexpr int NT = BN / 32;
    extern __shared__ __half sm[];

    const int tid = threadIdx.x;
    const int wid = tid >> 5;
    const int lane = tid & 31;
    const int wm = wid & 1;
    const int wn = wid >> 1;
    const int gid = lane >> 2;
    const int tig = lane & 3;
    const int m0 = blockIdx.y * BM;
    const int n0 = blockIdx.x * BN;
    const int nk = K / BK;

    const int a_row = wm * 32 + (lane & 7) + ((lane >> 3) & 1) * 8;
    const int a_koff = (lane & 16) >> 1;
    const int b_row = wn * (NT * 8) + (lane & 7) + ((lane & 16) >> 1);
    const int b_koff = lane & 8;

    float c[2][NT][4];
#pragma unroll
    for (int mt = 0; mt < 2; mt++)
#pragma unroll
        for (int nt = 0; nt < NT; nt++)
#pragma unroll
            for (int r = 0; r < 4; r++) c[mt][nt][r] = 0.f;

    auto load_stage = [&](int kc, int s) {
        const int k0 = kc * BK;
        __half* base = sm + s * STAGE;
        {
            int row = tid >> 2, ch = tid & 3;
            int gm = m0 + row;
            bool p = gm < M;
            int gmc = p ? gm : (M - 1);
            size_t goff = (size_t)gmc * K + k0 + ch * 8;
            uint32_t d = smem_u32(base + row * STR + ch * 8);
            cp_async16(d, Ahi + goff, p);
            cp_async16(d + ASZ * 2, Alo + goff, p);
        }
#pragma unroll
        for (int j = 0; j < BN / 64; j++) {
            int i = tid + j * 256;
            int row = i >> 2, ch = i & 3;
            size_t goff = (size_t)(n0 + row) * K + k0 + ch * 8;
            uint32_t d = smem_u32(base + 2 * ASZ + row * STR + ch * 8);
            cp_async16(d, Bh + goff, true);
        }
    };

    load_stage(0, 0);
    cp_commit();

    for (int kc = 0; kc < nk; kc++) {
        const int s = kc & 1;
        if (kc + 1 < nk) {
            load_stage(kc + 1, s ^ 1);
            cp_commit();
            cp_wait<1>();
        } else {
            cp_wait<0>();
        }
        __syncthreads();

        const uint32_t stg = smem_u32(sm + s * STAGE);
        const uint32_t ah_base = stg + (a_row * STR + a_koff) * 2;
        const uint32_t al_base = ah_base + ASZ * 2;
        const uint32_t bh_base = stg + 2 * ASZ * 2 + (b_row * STR + b_koff) * 2;

#pragma unroll
        for (int kb = 0; kb < BK; kb += 16) {
            uint32_t bfh[NT][2];
#pragma unroll
            for (int p = 0; p < NT / 2; p++) {
                uint32_t off = (p * 16 * STR + kb) * 2;
                ldsm_x4(&bfh[2 * p][0], bh_base + off);
            }
#pragma unroll
            for (int mt = 0; mt < 2; mt++) {
                uint32_t afh[4], afl[4];
                uint32_t off = (mt * 16 * STR + kb) * 2;
                ldsm_x4(afh, ah_base + off);
                ldsm_x4(afl, al_base + off);
#pragma unroll
                for (int nt = 0; nt < NT; nt++) {
                    mma_f16(c[mt][nt], afh, bfh[nt]);
                    mma_f16(c[mt][nt], afl, bfh[nt]);
                }
            }
        }
        __syncthreads();
    }

#pragma unroll
    for (int mt = 0; mt < 2; mt++) {
        int r0 = m0 + wm * 32 + mt * 16 + gid;
#pragma unroll
        for (int nt = 0; nt < NT; nt++) {
            int col = n0 + wn * (NT * 8) + nt * 8 + tig * 2;
            float b0 = bias[col], b1 = bias[col + 1];
            if (r0 < M) {
                float2 v0 = make_float2(c[mt][nt][0] + b0, c[mt][nt][1] + b1);
                *reinterpret_cast<float2*>(C + (size_t)r0 * N + col) = v0;
            }
            if (r0 + 8 < M) {
                float2 v1 = make_float2(c[mt][nt][2] + b0, c[mt][nt][3] + b1);
                *reinterpret_cast<float2*>(C + (size_t)(r0 + 8) * N + col) = v1;
            }
        }
    }
}

// ---------------- fused GATv2 edge-softmax + aggregation -------------------
// NWPN warps per node. Two-accumulator online softmax (even/odd edges) for
// ILP-2 on the exp chain; single exp per edge; pair prefetch of gathers.
template <int D, int NWPN>
__global__ void __launch_bounds__(256, 4)
k_agg(const float* __restrict__ xlr, int SR, int XO,
      const float* __restrict__ att, const float* __restrict__ bias,
      __half* __restrict__ ohi, __half* __restrict__ olo) {
    constexpr int CPL = D / (32 * NWPN);   // 4
    constexpr int LPH = 8 * NWPN;          // lanes per head group

    int gw = (blockIdx.x * blockDim.x + threadIdx.x) >> 5;
    int lane = threadIdx.x & 31;
    int node = gw / NWPN;
    int part = gw % NWPN;
    if (node >= NN) return;
    const int base = part * (D / NWPN) + lane * CPL;

    float attv[CPL], xrv[CPL];
    {
        float4 a4 = *reinterpret_cast<const float4*>(att + base);
        float4 r4 = *reinterpret_cast<const float4*>(xlr + (size_t)node * SR + XO + base);
        attv[0] = a4.x; attv[1] = a4.y; attv[2] = a4.z; attv[3] = a4.w;
        xrv[0] = r4.x; xrv[1] = r4.y; xrv[2] = r4.z; xrv[3] = r4.w;
    }

    const float NEGINF = -3.402823466e38f;
    float mA = NEGINF, sA = 0.f, mB = NEGINF, sB = 0.f;
    float accA[CPL], accB[CPL];
#pragma unroll
    for (int c = 0; c < CPL; c++) { accA[c] = 0.f; accB[c] = 0.f; }

    const int rs = g_rowptr[node];
    const int re = g_rowptr[node + 1];
    const int deg = re - rs;

    if (deg > 0) {
        // preload pair 0
        int c0 = g_col[rs];
        int c1 = g_col[(rs + 1 < re) ? rs + 1 : rs];
        float4 vA = *reinterpret_cast<const float4*>(xlr + (size_t)c0 * SR + base);
        float4 vB = *reinterpret_cast<const float4*>(xlr + (size_t)c1 * SR + base);

        for (int p = rs; p < re; p += 2) {
            // prefetch pair p+2
            int n0 = (p + 2 < re) ? g_col[p + 2] : c0;
            int n1 = (p + 3 < re) ? g_col[p + 3] : c0;
            float4 nA = *reinterpret_cast<const float4*>(xlr + (size_t)n0 * SR + base);
            float4 nB = *reinterpret_cast<const float4*>(xlr + (size_t)n1 * SR + base);

            // --- edge p -> state A ---
            {
                float xl0 = vA.x, xl1 = vA.y, xl2 = vA.z, xl3 = vA.w;
                float e0 = xl0 + xrv[0]; e0 = (e0 >= 0.f) ? e0 : 0.2f * e0;
                float e1 = xl1 + xrv[1]; e1 = (e1 >= 0.f) ? e1 : 0.2f * e1;
                float e2 = xl2 + xrv[2]; e2 = (e2 >= 0.f) ? e2 : 0.2f * e2;
                float e3 = xl3 + xrv[3]; e3 = (e3 >= 0.f) ? e3 : 0.2f * e3;
                float partial = attv[0] * e0;
                partial = fmaf(attv[1], e1, partial);
                partial = fmaf(attv[2], e2, partial);
                partial = fmaf(attv[3], e3, partial);
#pragma unroll
                for (int off = 1; off < LPH; off <<= 1)
                    partial += __shfl_xor_sync(0xffffffffu, partial, off);

                float mnew = fmaxf(mA, partial);
                float d = __expf(fminf(mA, partial) - mnew);
                bool nw = partial > mA;
                float fac = nw ? d : 1.f;
                float w = nw ? 1.f : d;
                sA = sA * fac + w;
                accA[0] = fmaf(accA[0], fac, w * xl0);
                accA[1] = fmaf(accA[1], fac, w * xl1);
                accA[2] = fmaf(accA[2], fac, w * xl2);
                accA[3] = fmaf(accA[3], fac, w * xl3);
                mA = mnew;
            }
            // --- edge p+1 -> state B (independent chain) ---
            if (p + 1 < re) {
                float xl0 = vB.x, xl1 = vB.y, xl2 = vB.z, xl3 = vB.w;
                float e0 = xl0 + xrv[0]; e0 = (e0 >= 0.f) ? e0 : 0.2f * e0;
                float e1 = xl1 + xrv[1]; e1 = (e1 >= 0.f) ? e1 : 0.2f * e1;
                float e2 = xl2 + xrv[2]; e2 = (e2 >= 0.f) ? e2 : 0.2f * e2;
                float e3 = xl3 + xrv[3]; e3 = (e3 >= 0.f) ? e3 : 0.2f * e3;
                float partial = attv[0] * e0;
                partial = fmaf(attv[1], e1, partial);
                partial = fmaf(attv[2], e2, partial);
                partial = fmaf(attv[3], e3, partial);
#pragma unroll
                for (int off = 1; off < LPH; off <<= 1)
                    partial += __shfl_xor_sync(0xffffffffu, partial, off);

                float mnew = fmaxf(mB, partial);
                float d = __expf(fminf(mB, partial) - mnew);
                bool nw = partial > mB;
                float fac = nw ? d : 1.f;
                float w = nw ? 1.f : d;
                sB = sB * fac + w;
                accB[0] = fmaf(accB[0], fac, w * xl0);
                accB[1] = fmaf(accB[1], fac, w * xl1);
                accB[2] = fmaf(accB[2], fac, w * xl2);
                accB[3] = fmaf(accB[3], fac, w * xl3);
                mB = mnew;
            }
            vA = nA; vB = nB;
            c0 = n0;
        }
    }

    // merge B into A (exact): guarded so deg==0 stays zeros
    float ssum = 0.f;
    float acc[CPL];
#pragma unroll
    for (int c = 0; c < CPL; c++) acc[c] = 0.f;
    if (deg > 0) {
        float mm = fmaxf(mA, mB);
        float dA = __expf(mA - mm);                       // mA finite
        float dB = (mB == NEGINF) ? 0.f : __expf(mB - mm);
        ssum = sA * dA + sB * dB;
#pragma unroll
        for (int c = 0; c < CPL; c++) acc[c] = accA[c] * dA + accB[c] * dB;
    }

    float inv = (ssum > 0.f) ? (1.f / ssum) : 0.f;
#pragma unroll
    for (int j = 0; j < CPL / 2; j++) {
        float v0 = fmaxf(fmaf(acc[2 * j], inv, bias[base + 2 * j]), 0.f);
        float v1 = fmaxf(fmaf(acc[2 * j + 1], inv, bias[base + 2 * j + 1]), 0.f);
        __half h0, l0, h1, l1;
        split1h(v0, h0, l0);
        split1h(v1, h1, l1);
        __half2 hp = __halves2half2(h0, h1);
        __half2 lp = __halves2half2(l0, l1);
        *reinterpret_cast<__half2*>(ohi + (size_t)node * D + base + 2 * j) = hp;
        *reinterpret_cast<__half2*>(olo + (size_t)node * D + base + 2 * j) = lp;
    }
}

// ---------------- launch ----------------
extern "C" void kernel_launch(void* const* d_in, const int* in_sizes, int n_in,
                              void* d_out, int out_size) {
    (void)in_sizes; (void)n_in; (void)out_size;
    const float* x     = (const float*)d_in[0];
    const int*   ei    = (const int*)  d_in[1];
    const float* Wl1   = (const float*)d_in[3];
    const float* bl1   = (const float*)d_in[4];
    const float* Wr1   = (const float*)d_in[5];
    const float* br1   = (const float*)d_in[6];
    const float* att1  = (const float*)d_in[7];
    const float* bias1 = (const float*)d_in[8];
    const float* Wl2   = (const float*)d_in[9];
    const float* bl2   = (const float*)d_in[10];
    const float* Wr2   = (const float*)d_in[11];
    const float* br2   = (const float*)d_in[12];
    const float* att2  = (const float*)d_in[13];
    const float* bias2 = (const float*)d_in[14];
    const float* Wlin  = (const float*)d_in[15];
    const float* blin  = (const float*)d_in[16];
    float* out = (float*)d_out;

    const int* src = ei;
    const int* dst = ei + NE;

    __half *xhi, *xlo, *h1hi, *h1lo, *h2hi, *h2lo;
    __half *wt1h, *wt2h, *wtlh;
    float *xlr1, *xlr2, *cb1, *cb2;
    cudaGetSymbolAddress((void**)&xhi, g_xhi);
    cudaGetSymbolAddress((void**)&xlo, g_xlo);
    cudaGetSymbolAddress((void**)&h1hi, g_h1hi);
    cudaGetSymbolAddress((void**)&h1lo, g_h1lo);
    cudaGetSymbolAddress((void**)&h2hi, g_h2hi);
    cudaGetSymbolAddress((void**)&h2lo, g_h2lo);
    cudaGetSymbolAddress((void**)&wt1h, g_wt1h);
    cudaGetSymbolAddress((void**)&wt2h, g_wt2h);
    cudaGetSymbolAddress((void**)&wtlh, g_wtlh);
    cudaGetSymbolAddress((void**)&xlr1, g_xlr1);
    cudaGetSymbolAddress((void**)&xlr2, g_xlr2);
    cudaGetSymbolAddress((void**)&cb1, g_cb1);
    cudaGetSymbolAddress((void**)&cb2, g_cb2);

    constexpr int SMEM128 = 2 * (2 * 64 * 40 + 128 * 40) * 2;  // 40960 B
    constexpr int SMEM64  = 2 * (2 * 64 * 40 + 64 * 40) * 2;   // 30720 B
    static cudaStream_t s_aux = nullptr;
    static cudaEvent_t e_fork = nullptr, e_csr = nullptr;
    if (!s_aux) {
        cudaFuncSetAttribute(gemm_f16<128>, cudaFuncAttributeMaxDynamicSharedMemorySize, SMEM128);
        cudaFuncSetAttribute(gemm_f16<64>,  cudaFuncAttributeMaxDynamicSharedMemorySize, SMEM64);
        cudaStreamCreateWithFlags(&s_aux, cudaStreamNonBlocking);
        cudaEventCreateWithFlags(&e_fork, cudaEventDisableTiming);
        cudaEventCreateWithFlags(&e_csr, cudaEventDisableTiming);
    }

    const int MB = (NN + 63) / 64;  // 313

    // #1: fused prep
    k_prep<<<(PREP_TOTAL + 255) / 256, 256>>>(x, Wl1, Wr1, Wl2, Wr2, Wlin, bl1, br1, bl2, br2);

    // fork CSR build onto side stream
    cudaEventRecord(e_fork, 0);
    cudaStreamWaitEvent(s_aux, e_fork, 0);
    k_hist<<<(NE + 255) / 256, 256, 0, s_aux>>>(dst);                 // #2
    k_scan<<<1, 1024, 0, s_aux>>>();                                  // #3

    // #4 (profiled slot): layer-1 GEMM (N=256 = [xl|xr])
    gemm_f16<128><<<dim3(2, MB), 256, SMEM128>>>(xhi, xlo, wt1h, cb1, xlr1, NN, 256, 128);

    k_scatter<<<(NE + 255) / 256, 256, 0, s_aux>>>(src, dst);         // #5
    cudaEventRecord(e_csr, s_aux);
    cudaStreamWaitEvent(0, e_csr, 0);

    // aggs: NWPN=1 (D=128), NWPN=4 (D=512, one warp per head)
    k_agg<128, 1><<<(NN * 32 + 255) / 256, 256>>>(xlr1, 256, 128, att1, bias1, h1hi, h1lo);
    gemm_f16<128><<<dim3(8, MB), 256, SMEM128>>>(h1hi, h1lo, wt2h, cb2, xlr2, NN, 1024, 128);
    k_agg<512, 4><<<(NN * 4 * 32 + 255) / 256, 256>>>(xlr2, 1024, 512, att2, bias2, h2hi, h2lo);
    gemm_f16<64><<<dim3(1, MB), 256, SMEM64>>>(h2hi, h2lo, wtlh, blin, out, NN, 64, 512);
}

// round 11
// speedup vs baseline: 1.0497x; 1.0497x over previous
#include <cuda_runtime.h>
#include <cuda_fp16.h>
#include <cstdint>

#define NN 20000
#define NE 160000

// ---------------- scratch (device globals: allocation-free) ----------------
__device__ __half g_xhi[NN * 128], g_xlo[NN * 128];
__device__ float g_xlr1[NN * 256];
__device__ __half g_h1hi[NN * 128], g_h1lo[NN * 128];
__device__ float g_xlr2[NN * 1024];
__device__ __half g_h2hi[NN * 512], g_h2lo[NN * 512];
__device__ __half g_wt1h[256 * 128];
__device__ __half g_wt2h[1024 * 128];
__device__ __half g_wtlh[64 * 512];
__device__ float g_cb1[256];
__device__ float g_cb2[1024];
__device__ int g_deg[NN];
__device__ int g_rowptr[NN + 1];
__device__ int g_cursor[NN];
__device__ int g_col[NE];

// ---------------- helpers ----------------
__device__ __forceinline__ uint32_t smem_u32(const void* p) {
    uint32_t a;
    asm("{ .reg .u64 t; cvta.to.shared.u64 t, %1; cvt.u32.u64 %0, t; }" : "=r"(a) : "l"(p));
    return a;
}
__device__ __forceinline__ void cp_async16(uint32_t dst, const void* src, bool pred) {
    int sz = pred ? 16 : 0;
    asm volatile("cp.async.cg.shared.global [%0], [%1], 16, %2;"
                 :: "r"(dst), "l"(src), "r"(sz) : "memory");
}
__device__ __forceinline__ void cp_commit() {
    asm volatile("cp.async.commit_group;" ::: "memory");
}
template <int W> __device__ __forceinline__ void cp_wait() {
    asm volatile("cp.async.wait_group %0;" :: "n"(W) : "memory");
}
__device__ __forceinline__ void split1h(float a, __half& h, __half& l) {
    h = __float2half_rn(a);
    l = __float2half_rn(a - __half2float(h));
}
__device__ __forceinline__ void mma_f16(float* c, const uint32_t* a, const uint32_t* b) {
    asm volatile("mma.sync.aligned.m16n8k16.row.col.f32.f16.f16.f32 "
                 "{%0,%1,%2,%3}, {%4,%5,%6,%7}, {%8,%9}, {%0,%1,%2,%3};"
                 : "+f"(c[0]), "+f"(c[1]), "+f"(c[2]), "+f"(c[3])
                 : "r"(a[0]), "r"(a[1]), "r"(a[2]), "r"(a[3]), "r"(b[0]), "r"(b[1]));
}
__device__ __forceinline__ void ldsm_x4(uint32_t* r, uint32_t addr) {
    asm volatile("ldmatrix.sync.aligned.m8n8.x4.shared.b16 {%0,%1,%2,%3}, [%4];"
                 : "=r"(r[0]), "=r"(r[1]), "=r"(r[2]), "=r"(r[3]) : "r"(addr));
}

// ---------------- fused prep: zero_deg + x split + W transposes + bias -----
__global__ void k_prep(const float* __restrict__ x,
                       const float* __restrict__ Wl1, const float* __restrict__ Wr1,
                       const float* __restrict__ Wl2, const float* __restrict__ Wr2,
                       const float* __restrict__ Wlin,
                       const float* __restrict__ bl1, const float* __restrict__ br1,
                       const float* __restrict__ bl2, const float* __restrict__ br2) {
    const int S0 = NN;
    const int S1 = S0 + NN * 128;
    const int S2 = S1 + 16384;
    const int S3 = S2 + 16384;
    const int S4 = S3 + 65536;
    const int S5 = S4 + 65536;
    const int S6 = S5 + 32768;
    const int S7 = S6 + 1280;
    int i = blockIdx.x * blockDim.x + threadIdx.x;
    if (i < S0) {
        g_deg[i] = 0;
    } else if (i < S1) {
        int j = i - S0;
        __half h, l;
        split1h(x[j], h, l);
        g_xhi[j] = h; g_xlo[j] = l;
    } else if (i < S2) {
        int j = i - S1, k = j >> 7, n = j & 127;
        g_wt1h[n * 128 + k] = __float2half_rn(Wl1[j]);
    } else if (i < S3) {
        int j = i - S2, k = j >> 7, n = j & 127;
        g_wt1h[128 * 128 + n * 128 + k] = __float2half_rn(Wr1[j]);
    } else if (i < S4) {
        int j = i - S3, k = j >> 9, n = j & 511;
        g_wt2h[n * 128 + k] = __float2half_rn(Wl2[j]);
    } else if (i < S5) {
        int j = i - S4, k = j >> 9, n = j & 511;
        g_wt2h[512 * 128 + n * 128 + k] = __float2half_rn(Wr2[j]);
    } else if (i < S6) {
        int j = i - S5, k = j >> 6, n = j & 63;
        g_wtlh[n * 512 + k] = __float2half_rn(Wlin[j]);
    } else if (i < S7) {
        int j = i - S6;
        if (j < 256) g_cb1[j] = (j < 128) ? bl1[j] : br1[j - 128];
        else {
            int b = j - 256;
            g_cb2[b] = (b < 512) ? bl2[b] : br2[b - 512];
        }
    }
}
#define PREP_TOTAL (NN + NN * 128 + 16384 * 2 + 65536 * 2 + 32768 + 1280)

// ---------------- CSR build (counting sort by dst) ----------------
__global__ void k_hist(const int* __restrict__ dst) {
    int e = blockIdx.x * blockDim.x + threadIdx.x;
    if (e < NE) atomicAdd(&g_deg[dst[e]], 1);
}
__global__ void k_scan() {
    __shared__ int s[1024];
    const int CH = (NN + 1023) / 1024;
    int t = threadIdx.x;
    int start = t * CH;
    int end = start + CH < NN ? start + CH : NN;
    int sum = 0;
    for (int i = start; i < end; i++) sum += g_deg[i];
    s[t] = sum;
    __syncthreads();
    for (int off = 1; off < 1024; off <<= 1) {
        int v = (t >= off) ? s[t - off] : 0;
        __syncthreads();
        s[t] += v;
        __syncthreads();
    }
    int run = (t == 0) ? 0 : s[t - 1];
    for (int i = start; i < end; i++) {
        g_rowptr[i] = run;
        g_cursor[i] = run;
        run += g_deg[i];
    }
    if (t == 1023) g_rowptr[NN] = s[1023];
}
__global__ void k_scatter(const int* __restrict__ src, const int* __restrict__ dst) {
    int e = blockIdx.x * blockDim.x + threadIdx.x;
    if (e < NE) {
        int d = dst[e];
        int pos = atomicAdd(&g_cursor[d], 1);
        g_col[pos] = src[e];
    }
}

// ---------------- pipelined fp16 2-MMA split GEMM (3-stage cp.async) ------
// C = (Ah + Al)[M,K] @ Bh[N,K]^T + bias. M-tile 64, BK=32, 3 CTAs/SM.
template <int BN>
__global__ void __launch_bounds__(256, 3)
gemm_f16(const __half* __restrict__ Ahi, const __half* __restrict__ Alo,
         const __half* __restrict__ Bh, const float* __restrict__ bias,
         float* __restrict__ C, int M, int N, int K) {
    constexpr int BM = 64;
    constexpr int BK = 32;
    constexpr int STR = 40;
    constexpr int ASZ = BM * STR;
    constexpr int BSZ = BN * STR;
    constexpr int STAGE = 2 * ASZ + BSZ;
    constexpr int NT = BN / 32;
    extern __shared__ __half sm[];

    const int tid = threadIdx.x;
    const int wid = tid >> 5;
    const int lane = tid & 31;
    const int wm = wid & 1;
    const int wn = wid >> 1;
    const int gid = lane >> 2;
    const int tig = lane & 3;
    const int m0 = blockIdx.y * BM;
    const int n0 = blockIdx.x * BN;
    const int nk = K / BK;

    const int a_row = wm * 32 + (lane & 7) + ((lane >> 3) & 1) * 8;
    const int a_koff = (lane & 16) >> 1;
    const int b_row = wn * (NT * 8) + (lane & 7) + ((lane & 16) >> 1);
    const int b_koff = lane & 8;

    float c[2][NT][4];
#pragma unroll
    for (int mt = 0; mt < 2; mt++)
#pragma unroll
        for (int nt = 0; nt < NT; nt++)
#pragma unroll
            for (int r = 0; r < 4; r++) c[mt][nt][r] = 0.f;

    auto load_stage = [&](int kc, int s) {
        const int k0 = kc * BK;
        __half* base = sm + s * STAGE;
        {
            int row = tid >> 2, ch = tid & 3;
            int gm = m0 + row;
            bool p = gm < M;
            int gmc = p ? gm : (M - 1);
            size_t goff = (size_t)gmc * K + k0 + ch * 8;
            uint32_t d = smem_u32(base + row * STR + ch * 8);
            cp_async16(d, Ahi + goff, p);
            cp_async16(d + ASZ * 2, Alo + goff, p);
        }
#pragma unroll
        for (int j = 0; j < BN / 64; j++) {
            int i = tid + j * 256;
            int row = i >> 2, ch = i & 3;
            size_t goff = (size_t)(n0 + row) * K + k0 + ch * 8;
            uint32_t d = smem_u32(base + 2 * ASZ + row * STR + ch * 8);
            cp_async16(d, Bh + goff, true);
        }
    };

    // prime 2 stages
    load_stage(0, 0);
    cp_commit();
    if (nk > 1) {
        load_stage(1, 1);
        cp_commit();
    }

    int s = 0;
    for (int kc = 0; kc < nk; kc++) {
        if (kc + 2 < nk) {
            load_stage(kc + 2, (kc + 2) % 3);
            cp_commit();
            cp_wait<2>();
        } else if (kc + 1 < nk) {
            cp_wait<1>();
        } else {
            cp_wait<0>();
        }
        __syncthreads();

        const uint32_t stg = smem_u32(sm + s * STAGE);
        const uint32_t ah_base = stg + (a_row * STR + a_koff) * 2;
        const uint32_t al_base = ah_base + ASZ * 2;
        const uint32_t bh_base = stg + 2 * ASZ * 2 + (b_row * STR + b_koff) * 2;

#pragma unroll
        for (int kb = 0; kb < BK; kb += 16) {
            uint32_t bfh[NT][2];
#pragma unroll
            for (int p = 0; p < NT / 2; p++) {
                uint32_t off = (p * 16 * STR + kb) * 2;
                ldsm_x4(&bfh[2 * p][0], bh_base + off);
            }
#pragma unroll
            for (int mt = 0; mt < 2; mt++) {
                uint32_t afh[4], afl[4];
                uint32_t off = (mt * 16 * STR + kb) * 2;
                ldsm_x4(afh, ah_base + off);
                ldsm_x4(afl, al_base + off);
#pragma unroll
                for (int nt = 0; nt < NT; nt++) {
                    mma_f16(c[mt][nt], afh, bfh[nt]);
                    mma_f16(c[mt][nt], afl, bfh[nt]);
                }
            }
        }
        __syncthreads();
        s = (s + 1) % 3;
    }

#pragma unroll
    for (int mt = 0; mt < 2; mt++) {
        int r0 = m0 + wm * 32 + mt * 16 + gid;
#pragma unroll
        for (int nt = 0; nt < NT; nt++) {
            int col = n0 + wn * (NT * 8) + nt * 8 + tig * 2;
            float b0 = bias[col], b1 = bias[col + 1];
            if (r0 < M) {
                float2 v0 = make_float2(c[mt][nt][0] + b0, c[mt][nt][1] + b1);
                *reinterpret_cast<float2*>(C + (size_t)r0 * N + col) = v0;
            }
            if (r0 + 8 < M) {
                float2 v1 = make_float2(c[mt][nt][2] + b0, c[mt][nt][3] + b1);
                *reinterpret_cast<float2*>(C + (size_t)(r0 + 8) * N + col) = v1;
            }
        }
    }
}

// ---------------- fused GATv2 edge-softmax + aggregation (R9 version) ------
template <int D, int NWPN>
__global__ void __launch_bounds__(256, 3)
k_agg(const float* __restrict__ xlr, int SR, int XO,
      const float* __restrict__ att, const float* __restrict__ bias,
      __half* __restrict__ ohi, __half* __restrict__ olo) {
    constexpr int CPL = D / (32 * NWPN);
    constexpr int V = CPL / 4;
    constexpr int LPH = 8 * NWPN;

    int gw = (blockIdx.x * blockDim.x + threadIdx.x) >> 5;
    int lane = threadIdx.x & 31;
    int node = gw / NWPN;
    int part = gw % NWPN;
    if (node >= NN) return;
    const int base = part * (D / NWPN) + lane * CPL;

    float attv[CPL], xrv[CPL];
#pragma unroll
    for (int j = 0; j < V; j++) {
        float4 a4 = *reinterpret_cast<const float4*>(att + base + 4 * j);
        float4 r4 = *reinterpret_cast<const float4*>(xlr + (size_t)node * SR + XO + base + 4 * j);
        attv[4 * j + 0] = a4.x; attv[4 * j + 1] = a4.y;
        attv[4 * j + 2] = a4.z; attv[4 * j + 3] = a4.w;
        xrv[4 * j + 0] = r4.x; xrv[4 * j + 1] = r4.y;
        xrv[4 * j + 2] = r4.z; xrv[4 * j + 3] = r4.w;
    }

    float m = -3.402823466e38f;
    float ssum = 0.f;
    float acc[CPL];
#pragma unroll
    for (int c = 0; c < CPL; c++) acc[c] = 0.f;

    const int rs = g_rowptr[node];
    const int re = g_rowptr[node + 1];

    if (rs < re) {
        int s = g_col[rs];
        float xlv[CPL];
#pragma unroll
        for (int j = 0; j < V; j++) {
            float4 v = *reinterpret_cast<const float4*>(xlr + (size_t)s * SR + base + 4 * j);
            xlv[4 * j + 0] = v.x; xlv[4 * j + 1] = v.y;
            xlv[4 * j + 2] = v.z; xlv[4 * j + 3] = v.w;
        }
        for (int p = rs; p < re; p++) {
            int sn = (p + 1 < re) ? g_col[p + 1] : s;
            float xln[CPL];
#pragma unroll
            for (int j = 0; j < V; j++) {
                float4 v = *reinterpret_cast<const float4*>(xlr + (size_t)sn * SR + base + 4 * j);
                xln[4 * j + 0] = v.x; xln[4 * j + 1] = v.y;
                xln[4 * j + 2] = v.z; xln[4 * j + 3] = v.w;
            }
            float partial = 0.f;
#pragma unroll
            for (int c = 0; c < CPL; c++) {
                float e = xlv[c] + xrv[c];
                e = (e >= 0.f) ? e : 0.2f * e;
                partial = fmaf(attv[c], e, partial);
            }
#pragma unroll
            for (int off = 1; off < LPH; off <<= 1)
                partial += __shfl_xor_sync(0xffffffffu, partial, off);

            float mnew = fmaxf(m, partial);
            float fac = __expf(m - mnew);
            float w = __expf(partial - mnew);
            ssum = ssum * fac + w;
#pragma unroll
            for (int c = 0; c < CPL; c++) acc[c] = fmaf(acc[c], fac, w * xlv[c]);
            m = mnew;
#pragma unroll
            for (int c = 0; c < CPL; c++) xlv[c] = xln[c];
        }
    }

    float inv = (ssum > 0.f) ? (1.f / ssum) : 0.f;
#pragma unroll
    for (int j = 0; j < CPL / 2; j++) {
        float v0 = fmaxf(fmaf(acc[2 * j], inv, bias[base + 2 * j]), 0.f);
        float v1 = fmaxf(fmaf(acc[2 * j + 1], inv, bias[base + 2 * j + 1]), 0.f);
        __half h0, l0, h1, l1;
        split1h(v0, h0, l0);
        split1h(v1, h1, l1);
        __half2 hp = __halves2half2(h0, h1);
        __half2 lp = __halves2half2(l0, l1);
        *reinterpret_cast<__half2*>(ohi + (size_t)node * D + base + 2 * j) = hp;
        *reinterpret_cast<__half2*>(olo + (size_t)node * D + base + 2 * j) = lp;
    }
}

// ---------------- launch ----------------
extern "C" void kernel_launch(void* const* d_in, const int* in_sizes, int n_in,
                              void* d_out, int out_size) {
    (void)in_sizes; (void)n_in; (void)out_size;
    const float* x     = (const float*)d_in[0];
    const int*   ei    = (const int*)  d_in[1];
    const float* Wl1   = (const float*)d_in[3];
    const float* bl1   = (const float*)d_in[4];
    const float* Wr1   = (const float*)d_in[5];
    const float* br1   = (const float*)d_in[6];
    const float* att1  = (const float*)d_in[7];
    const float* bias1 = (const float*)d_in[8];
    const float* Wl2   = (const float*)d_in[9];
    const float* bl2   = (const float*)d_in[10];
    const float* Wr2   = (const float*)d_in[11];
    const float* br2   = (const float*)d_in[12];
    const float* att2  = (const float*)d_in[13];
    const float* bias2 = (const float*)d_in[14];
    const float* Wlin  = (const float*)d_in[15];
    const float* blin  = (const float*)d_in[16];
    float* out = (float*)d_out;

    const int* src = ei;
    const int* dst = ei + NE;

    __half *xhi, *xlo, *h1hi, *h1lo, *h2hi, *h2lo;
    __half *wt1h, *wt2h, *wtlh;
    float *xlr1, *xlr2, *cb1, *cb2;
    cudaGetSymbolAddress((void**)&xhi, g_xhi);
    cudaGetSymbolAddress((void**)&xlo, g_xlo);
    cudaGetSymbolAddress((void**)&h1hi, g_h1hi);
    cudaGetSymbolAddress((void**)&h1lo, g_h1lo);
    cudaGetSymbolAddress((void**)&h2hi, g_h2hi);
    cudaGetSymbolAddress((void**)&h2lo, g_h2lo);
    cudaGetSymbolAddress((void**)&wt1h, g_wt1h);
    cudaGetSymbolAddress((void**)&wt2h, g_wt2h);
    cudaGetSymbolAddress((void**)&wtlh, g_wtlh);
    cudaGetSymbolAddress((void**)&xlr1, g_xlr1);
    cudaGetSymbolAddress((void**)&xlr2, g_xlr2);
    cudaGetSymbolAddress((void**)&cb1, g_cb1);
    cudaGetSymbolAddress((void**)&cb2, g_cb2);

    constexpr int SMEM128 = 3 * (2 * 64 * 40 + 128 * 40) * 2;  // 61440 B
    constexpr int SMEM64  = 3 * (2 * 64 * 40 + 64 * 40) * 2;   // 46080 B
    static cudaStream_t s_aux = nullptr;
    static cudaEvent_t e_fork = nullptr, e_csr = nullptr;
    if (!s_aux) {
        cudaFuncSetAttribute(gemm_f16<128>, cudaFuncAttributeMaxDynamicSharedMemorySize, SMEM128);
        cudaFuncSetAttribute(gemm_f16<64>,  cudaFuncAttributeMaxDynamicSharedMemorySize, SMEM64);
        cudaStreamCreateWithFlags(&s_aux, cudaStreamNonBlocking);
        cudaEventCreateWithFlags(&e_fork, cudaEventDisableTiming);
        cudaEventCreateWithFlags(&e_csr, cudaEventDisableTiming);
    }

    const int MB = (NN + 63) / 64;  // 313

    // #1: fused prep
    k_prep<<<(PREP_TOTAL + 255) / 256, 256>>>(x, Wl1, Wr1, Wl2, Wr2, Wlin, bl1, br1, bl2, br2);

    // fork CSR build onto side stream
    cudaEventRecord(e_fork, 0);
    cudaStreamWaitEvent(s_aux, e_fork, 0);
    k_hist<<<(NE + 255) / 256, 256, 0, s_aux>>>(dst);                 // #2
    k_scan<<<1, 1024, 0, s_aux>>>();                                  // #3

    // #4 (profiled slot): layer-1 GEMM (N=256 = [xl|xr])
    gemm_f16<128><<<dim3(2, MB), 256, SMEM128>>>(xhi, xlo, wt1h, cb1, xlr1, NN, 256, 128);

    k_scatter<<<(NE + 255) / 256, 256, 0, s_aux>>>(src, dst);         // #5
    cudaEventRecord(e_csr, s_aux);
    cudaStreamWaitEvent(0, e_csr, 0);

    k_agg<128, 1><<<(NN * 32 + 255) / 256, 256>>>(xlr1, 256, 128, att1, bias1, h1hi, h1lo);
    gemm_f16<128><<<dim3(8, MB), 256, SMEM128>>>(h1hi, h1lo, wt2h, cb2, xlr2, NN, 1024, 128);
    k_agg<512, 2><<<(NN * 2 * 32 + 255) / 256, 256>>>(xlr2, 1024, 512, att2, bias2, h2hi, h2lo);
    gemm_f16<64><<<dim3(1, MB), 256, SMEM64>>>(h2hi, h2lo, wtlh, blin, out, NN, 64, 512);
}

// round 12
// speedup vs baseline: 1.1599x; 1.1050x over previous
#include <cuda_runtime.h>
#include <cuda_fp16.h>
#include <cstdint>

#define NN 20000
#define NE 160000

// ---------------- scratch (device globals: allocation-free) ----------------
__device__ __half g_xhi[NN * 128], g_xlo[NN * 128];
__device__ float g_xlr1[NN * 256];
__device__ __half g_h1hi[NN * 128], g_h1lo[NN * 128];
__device__ __half g_xlr2h[NN * 1024];
__device__ __half g_h2hi[NN * 512], g_h2lo[NN * 512];
__device__ __half g_wt1h[256 * 128];
__device__ __half g_wt2h[1024 * 128];
__device__ __half g_wtlh[64 * 512];
__device__ float g_cb1[256];
__device__ float g_cb2[1024];
__device__ int g_deg[NN];
__device__ int g_rowptr[NN + 1];
__device__ int g_cursor[NN];
__device__ int g_col[NE];

// ---------------- helpers ----------------
__device__ __forceinline__ uint32_t smem_u32(const void* p) {
    uint32_t a;
    asm("{ .reg .u64 t; cvta.to.shared.u64 t, %1; cvt.u32.u64 %0, t; }" : "=r"(a) : "l"(p));
    return a;
}
__device__ __forceinline__ void cp_async16(uint32_t dst, const void* src, bool pred) {
    int sz = pred ? 16 : 0;
    asm volatile("cp.async.cg.shared.global [%0], [%1], 16, %2;"
                 :: "r"(dst), "l"(src), "r"(sz) : "memory");
}
__device__ __forceinline__ void cp_commit() {
    asm volatile("cp.async.commit_group;" ::: "memory");
}
template <int W> __device__ __forceinline__ void cp_wait() {
    asm volatile("cp.async.wait_group %0;" :: "n"(W) : "memory");
}
__device__ __forceinline__ void split1h(float a, __half& h, __half& l) {
    h = __float2half_rn(a);
    l = __float2half_rn(a - __half2float(h));
}
__device__ __forceinline__ void mma_f16(float* c, const uint32_t* a, const uint32_t* b) {
    asm volatile("mma.sync.aligned.m16n8k16.row.col.f32.f16.f16.f32 "
                 "{%0,%1,%2,%3}, {%4,%5,%6,%7}, {%8,%9}, {%0,%1,%2,%3};"
                 : "+f"(c[0]), "+f"(c[1]), "+f"(c[2]), "+f"(c[3])
                 : "r"(a[0]), "r"(a[1]), "r"(a[2]), "r"(a[3]), "r"(b[0]), "r"(b[1]));
}
__device__ __forceinline__ void ldsm_x4(uint32_t* r, uint32_t addr) {
    asm volatile("ldmatrix.sync.aligned.m8n8.x4.shared.b16 {%0,%1,%2,%3}, [%4];"
                 : "=r"(r[0]), "=r"(r[1]), "=r"(r[2]), "=r"(r[3]) : "r"(addr));
}

// ---------------- fused prep: zero_deg + x split + W transposes + bias -----
__global__ void k_prep(const float* __restrict__ x,
                       const float* __restrict__ Wl1, const float* __restrict__ Wr1,
                       const float* __restrict__ Wl2, const float* __restrict__ Wr2,
                       const float* __restrict__ Wlin,
                       const float* __restrict__ bl1, const float* __restrict__ br1,
                       const float* __restrict__ bl2, const float* __restrict__ br2) {
    const int S0 = NN;
    const int S1 = S0 + NN * 128;
    const int S2 = S1 + 16384;
    const int S3 = S2 + 16384;
    const int S4 = S3 + 65536;
    const int S5 = S4 + 65536;
    const int S6 = S5 + 32768;
    const int S7 = S6 + 1280;
    int i = blockIdx.x * blockDim.x + threadIdx.x;
    if (i < S0) {
        g_deg[i] = 0;
    } else if (i < S1) {
        int j = i - S0;
        __half h, l;
        split1h(x[j], h, l);
        g_xhi[j] = h; g_xlo[j] = l;
    } else if (i < S2) {
        int j = i - S1, k = j >> 7, n = j & 127;
        g_wt1h[n * 128 + k] = __float2half_rn(Wl1[j]);
    } else if (i < S3) {
        int j = i - S2, k = j >> 7, n = j & 127;
        g_wt1h[128 * 128 + n * 128 + k] = __float2half_rn(Wr1[j]);
    } else if (i < S4) {
        int j = i - S3, k = j >> 9, n = j & 511;
        g_wt2h[n * 128 + k] = __float2half_rn(Wl2[j]);
    } else if (i < S5) {
        int j = i - S4, k = j >> 9, n = j & 511;
        g_wt2h[512 * 128 + n * 128 + k] = __float2half_rn(Wr2[j]);
    } else if (i < S6) {
        int j = i - S5, k = j >> 6, n = j & 63;
        g_wtlh[n * 512 + k] = __float2half_rn(Wlin[j]);
    } else if (i < S7) {
        int j = i - S6;
        if (j < 256) g_cb1[j] = (j < 128) ? bl1[j] : br1[j - 128];
        else {
            int b = j - 256;
            g_cb2[b] = (b < 512) ? bl2[b] : br2[b - 512];
        }
    }
}
#define PREP_TOTAL (NN + NN * 128 + 16384 * 2 + 65536 * 2 + 32768 + 1280)

// ---------------- CSR build (counting sort by dst) ----------------
__global__ void k_hist(const int* __restrict__ dst) {
    int e = blockIdx.x * blockDim.x + threadIdx.x;
    if (e < NE) atomicAdd(&g_deg[dst[e]], 1);
}
__global__ void k_scan() {
    __shared__ int s[1024];
    const int CH = (NN + 1023) / 1024;
    int t = threadIdx.x;
    int start = t * CH;
    int end = start + CH < NN ? start + CH : NN;
    int sum = 0;
    for (int i = start; i < end; i++) sum += g_deg[i];
    s[t] = sum;
    __syncthreads();
    for (int off = 1; off < 1024; off <<= 1) {
        int v = (t >= off) ? s[t - off] : 0;
        __syncthreads();
        s[t] += v;
        __syncthreads();
    }
    int run = (t == 0) ? 0 : s[t - 1];
    for (int i = start; i < end; i++) {
        g_rowptr[i] = run;
        g_cursor[i] = run;
        run += g_deg[i];
    }
    if (t == 1023) g_rowptr[NN] = s[1023];
}
__global__ void k_scatter(const int* __restrict__ src, const int* __restrict__ dst) {
    int e = blockIdx.x * blockDim.x + threadIdx.x;
    if (e < NE) {
        int d = dst[e];
        int pos = atomicAdd(&g_cursor[d], 1);
        g_col[pos] = src[e];
    }
}

// ---------------- pipelined fp16 2-MMA split GEMM (R9 2-stage) ------------
// C = (Ah + Al)[M,K] @ Bh[N,K]^T + bias. HOUT: store __half instead of float.
template <int BN, bool HOUT>
__global__ void __launch_bounds__(256, 3)
gemm_f16(const __half* __restrict__ Ahi, const __half* __restrict__ Alo,
         const __half* __restrict__ Bh, const float* __restrict__ bias,
         void* __restrict__ Cv, int M, int N, int K) {
    constexpr int BM = 64;
    constexpr int BK = 32;
    constexpr int STR = 40;
    constexpr int ASZ = BM * STR;
    constexpr int BSZ = BN * STR;
    constexpr int STAGE = 2 * ASZ + BSZ;
    constexpr int NT = BN / 32;
    extern __shared__ __half sm[];

    const int tid = threadIdx.x;
    const int wid = tid >> 5;
    const int lane = tid & 31;
    const int wm = wid & 1;
    const int wn = wid >> 1;
    const int gid = lane >> 2;
    const int tig = lane & 3;
    const int m0 = blockIdx.y * BM;
    const int n0 = blockIdx.x * BN;
    const int nk = K / BK;

    const int a_row = wm * 32 + (lane & 7) + ((lane >> 3) & 1) * 8;
    const int a_koff = (lane & 16) >> 1;
    const int b_row = wn * (NT * 8) + (lane & 7) + ((lane & 16) >> 1);
    const int b_koff = lane & 8;

    float c[2][NT][4];
#pragma unroll
    for (int mt = 0; mt < 2; mt++)
#pragma unroll
        for (int nt = 0; nt < NT; nt++)
#pragma unroll
            for (int r = 0; r < 4; r++) c[mt][nt][r] = 0.f;

    auto load_stage = [&](int kc, int s) {
        const int k0 = kc * BK;
        __half* base = sm + s * STAGE;
        {
            int row = tid >> 2, ch = tid & 3;
            int gm = m0 + row;
            bool p = gm < M;
            int gmc = p ? gm : (M - 1);
            size_t goff = (size_t)gmc * K + k0 + ch * 8;
            uint32_t d = smem_u32(base + row * STR + ch * 8);
            cp_async16(d, Ahi + goff, p);
            cp_async16(d + ASZ * 2, Alo + goff, p);
        }
#pragma unroll
        for (int j = 0; j < BN / 64; j++) {
            int i = tid + j * 256;
            int row = i >> 2, ch = i & 3;
            size_t goff = (size_t)(n0 + row) * K + k0 + ch * 8;
            uint32_t d = smem_u32(base + 2 * ASZ + row * STR + ch * 8);
            cp_async16(d, Bh + goff, true);
        }
    };

    load_stage(0, 0);
    cp_commit();

    for (int kc = 0; kc < nk; kc++) {
        const int s = kc & 1;
        if (kc + 1 < nk) {
            load_stage(kc + 1, s ^ 1);
            cp_commit();
            cp_wait<1>();
        } else {
            cp_wait<0>();
        }
        __syncthreads();

        const uint32_t stg = smem_u32(sm + s * STAGE);
        const uint32_t ah_base = stg + (a_row * STR + a_koff) * 2;
        const uint32_t al_base = ah_base + ASZ * 2;
        const uint32_t bh_base = stg + 2 * ASZ * 2 + (b_row * STR + b_koff) * 2;

#pragma unroll
        for (int kb = 0; kb < BK; kb += 16) {
            uint32_t bfh[NT][2];
#pragma unroll
            for (int p = 0; p < NT / 2; p++) {
                uint32_t off = (p * 16 * STR + kb) * 2;
                ldsm_x4(&bfh[2 * p][0], bh_base + off);
            }
#pragma unroll
            for (int mt = 0; mt < 2; mt++) {
                uint32_t afh[4], afl[4];
                uint32_t off = (mt * 16 * STR + kb) * 2;
                ldsm_x4(afh, ah_base + off);
                ldsm_x4(afl, al_base + off);
#pragma unroll
                for (int nt = 0; nt < NT; nt++) {
                    mma_f16(c[mt][nt], afh, bfh[nt]);
                    mma_f16(c[mt][nt], afl, bfh[nt]);
                }
            }
        }
        __syncthreads();
    }

#pragma unroll
    for (int mt = 0; mt < 2; mt++) {
        int r0 = m0 + wm * 32 + mt * 16 + gid;
#pragma unroll
        for (int nt = 0; nt < NT; nt++) {
            int col = n0 + wn * (NT * 8) + nt * 8 + tig * 2;
            float b0 = bias[col], b1 = bias[col + 1];
            if (HOUT) {
                __half* Ch = (__half*)Cv;
                if (r0 < M)
                    *reinterpret_cast<__half2*>(Ch + (size_t)r0 * N + col) =
                        __floats2half2_rn(c[mt][nt][0] + b0, c[mt][nt][1] + b1);
                if (r0 + 8 < M)
                    *reinterpret_cast<__half2*>(Ch + (size_t)(r0 + 8) * N + col) =
                        __floats2half2_rn(c[mt][nt][2] + b0, c[mt][nt][3] + b1);
            } else {
                float* Cf = (float*)Cv;
                if (r0 < M) {
                    float2 v0 = make_float2(c[mt][nt][0] + b0, c[mt][nt][1] + b1);
                    *reinterpret_cast<float2*>(Cf + (size_t)r0 * N + col) = v0;
                }
                if (r0 + 8 < M) {
                    float2 v1 = make_float2(c[mt][nt][2] + b0, c[mt][nt][3] + b1);
                    *reinterpret_cast<float2*>(Cf + (size_t)(r0 + 8) * N + col) = v1;
                }
            }
        }
    }
}

// ---------------- layer-1 agg (fp32 xlr, R9 version, D=128, NWPN=1) --------
__global__ void __launch_bounds__(256, 3)
k_agg1(const float* __restrict__ xlr,
       const float* __restrict__ att, const float* __restrict__ bias,
       __half* __restrict__ ohi, __half* __restrict__ olo) {
    constexpr int D = 128, SR = 256, XO = 128;
    constexpr int CPL = 4;

    int warp = (blockIdx.x * blockDim.x + threadIdx.x) >> 5;
    int lane = threadIdx.x & 31;
    if (warp >= NN) return;
    const int node = warp;
    const int base = lane * CPL;

    float attv[CPL], xrv[CPL];
    {
        float4 a4 = *reinterpret_cast<const float4*>(att + base);
        float4 r4 = *reinterpret_cast<const float4*>(xlr + (size_t)node * SR + XO + base);
        attv[0] = a4.x; attv[1] = a4.y; attv[2] = a4.z; attv[3] = a4.w;
        xrv[0] = r4.x; xrv[1] = r4.y; xrv[2] = r4.z; xrv[3] = r4.w;
    }

    float m = -3.402823466e38f;
    float ssum = 0.f;
    float acc[CPL];
#pragma unroll
    for (int c = 0; c < CPL; c++) acc[c] = 0.f;

    const int rs = g_rowptr[node];
    const int re = g_rowptr[node + 1];

    if (rs < re) {
        int s = g_col[rs];
        float4 cur = *reinterpret_cast<const float4*>(xlr + (size_t)s * SR + base);
        for (int p = rs; p < re; p++) {
            int sn = (p + 1 < re) ? g_col[p + 1] : s;
            float4 nxt = *reinterpret_cast<const float4*>(xlr + (size_t)sn * SR + base);
            float xlv[CPL] = {cur.x, cur.y, cur.z, cur.w};
            float partial = 0.f;
#pragma unroll
            for (int c = 0; c < CPL; c++) {
                float e = xlv[c] + xrv[c];
                e = (e >= 0.f) ? e : 0.2f * e;
                partial = fmaf(attv[c], e, partial);
            }
            partial += __shfl_xor_sync(0xffffffffu, partial, 1);
            partial += __shfl_xor_sync(0xffffffffu, partial, 2);
            partial += __shfl_xor_sync(0xffffffffu, partial, 4);

            float mnew = fmaxf(m, partial);
            float fac = __expf(m - mnew);
            float w = __expf(partial - mnew);
            ssum = ssum * fac + w;
#pragma unroll
            for (int c = 0; c < CPL; c++) acc[c] = fmaf(acc[c], fac, w * xlv[c]);
            m = mnew;
            cur = nxt;
        }
    }

    float inv = (ssum > 0.f) ? (1.f / ssum) : 0.f;
#pragma unroll
    for (int j = 0; j < CPL / 2; j++) {
        float v0 = fmaxf(fmaf(acc[2 * j], inv, bias[base + 2 * j]), 0.f);
        float v1 = fmaxf(fmaf(acc[2 * j + 1], inv, bias[base + 2 * j + 1]), 0.f);
        __half h0, l0, h1, l1;
        split1h(v0, h0, l0);
        split1h(v1, h1, l1);
        *reinterpret_cast<__half2*>(ohi + (size_t)node * D + base + 2 * j) = __halves2half2(h0, h1);
        *reinterpret_cast<__half2*>(olo + (size_t)node * D + base + 2 * j) = __halves2half2(l0, l1);
    }
}

// ---------------- layer-2 agg (fp16 xlr storage, D=512, NWPN=2) ------------
__global__ void __launch_bounds__(256, 3)
k_agg2(const __half* __restrict__ xlrh,
       const float* __restrict__ att, const float* __restrict__ bias,
       __half* __restrict__ ohi, __half* __restrict__ olo) {
    constexpr int D = 512, SR = 1024, XO = 512;
    constexpr int CPL = 8;     // halves per lane (16 B)
    constexpr int LPH = 16;

    int gw = (blockIdx.x * blockDim.x + threadIdx.x) >> 5;
    int lane = threadIdx.x & 31;
    int node = gw >> 1;
    int part = gw & 1;
    if (node >= NN) return;
    const int base = part * 256 + lane * CPL;

    float attv[CPL], xrv[CPL];
    {
        float4 a0 = *reinterpret_cast<const float4*>(att + base);
        float4 a1 = *reinterpret_cast<const float4*>(att + base + 4);
        attv[0] = a0.x; attv[1] = a0.y; attv[2] = a0.z; attv[3] = a0.w;
        attv[4] = a1.x; attv[5] = a1.y; attv[6] = a1.z; attv[7] = a1.w;
        uint4 r = *reinterpret_cast<const uint4*>(xlrh + (size_t)node * SR + XO + base);
        const __half2* rp = reinterpret_cast<const __half2*>(&r);
#pragma unroll
        for (int j = 0; j < 4; j++) {
            float2 f = __half22float2(rp[j]);
            xrv[2 * j] = f.x; xrv[2 * j + 1] = f.y;
        }
    }

    float m = -3.402823466e38f;
    float ssum = 0.f;
    float acc[CPL];
#pragma unroll
    for (int c = 0; c < CPL; c++) acc[c] = 0.f;

    const int rs = g_rowptr[node];
    const int re = g_rowptr[node + 1];

    if (rs < re) {
        int s = g_col[rs];
        uint4 cur = *reinterpret_cast<const uint4*>(xlrh + (size_t)s * SR + base);
        for (int p = rs; p < re; p++) {
            int sn = (p + 1 < re) ? g_col[p + 1] : s;
            uint4 nxt = *reinterpret_cast<const uint4*>(xlrh + (size_t)sn * SR + base);

            float xlv[CPL];
            const __half2* cp = reinterpret_cast<const __half2*>(&cur);
#pragma unroll
            for (int j = 0; j < 4; j++) {
                float2 f = __half22float2(cp[j]);
                xlv[2 * j] = f.x; xlv[2 * j + 1] = f.y;
            }
            float partial = 0.f;
#pragma unroll
            for (int c = 0; c < CPL; c++) {
                float e = xlv[c] + xrv[c];
                e = (e >= 0.f) ? e : 0.2f * e;
                partial = fmaf(attv[c], e, partial);
            }
            partial += __shfl_xor_sync(0xffffffffu, partial, 1);
            partial += __shfl_xor_sync(0xffffffffu, partial, 2);
            partial += __shfl_xor_sync(0xffffffffu, partial, 4);
            partial += __shfl_xor_sync(0xffffffffu, partial, 8);

            float mnew = fmaxf(m, partial);
            float fac = __expf(m - mnew);
            float w = __expf(partial - mnew);
            ssum = ssum * fac + w;
#pragma unroll
            for (int c = 0; c < CPL; c++) acc[c] = fmaf(acc[c], fac, w * xlv[c]);
            m = mnew;
            cur = nxt;
        }
    }

    float inv = (ssum > 0.f) ? (1.f / ssum) : 0.f;
#pragma unroll
    for (int j = 0; j < CPL / 2; j++) {
        float v0 = fmaxf(fmaf(acc[2 * j], inv, bias[base + 2 * j]), 0.f);
        float v1 = fmaxf(fmaf(acc[2 * j + 1], inv, bias[base + 2 * j + 1]), 0.f);
        __half h0, l0, h1, l1;
        split1h(v0, h0, l0);
        split1h(v1, h1, l1);
        *reinterpret_cast<__half2*>(ohi + (size_t)node * 512 + base + 2 * j) = __halves2half2(h0, h1);
        *reinterpret_cast<__half2*>(olo + (size_t)node * 512 + base + 2 * j) = __halves2half2(l0, l1);
    }
}

// ---------------- launch ----------------
extern "C" void kernel_launch(void* const* d_in, const int* in_sizes, int n_in,
                              void* d_out, int out_size) {
    (void)in_sizes; (void)n_in; (void)out_size;
    const float* x     = (const float*)d_in[0];
    const int*   ei    = (const int*)  d_in[1];
    const float* Wl1   = (const float*)d_in[3];
    const float* bl1   = (const float*)d_in[4];
    const float* Wr1   = (const float*)d_in[5];
    const float* br1   = (const float*)d_in[6];
    const float* att1  = (const float*)d_in[7];
    const float* bias1 = (const float*)d_in[8];
    const float* Wl2   = (const float*)d_in[9];
    const float* bl2   = (const float*)d_in[10];
    const float* Wr2   = (const float*)d_in[11];
    const float* br2   = (const float*)d_in[12];
    const float* att2  = (const float*)d_in[13];
    const float* bias2 = (const float*)d_in[14];
    const float* Wlin  = (const float*)d_in[15];
    const float* blin  = (const float*)d_in[16];
    float* out = (float*)d_out;

    const int* src = ei;
    const int* dst = ei + NE;

    __half *xhi, *xlo, *h1hi, *h1lo, *h2hi, *h2lo, *xlr2h;
    __half *wt1h, *wt2h, *wtlh;
    float *xlr1, *cb1, *cb2;
    cudaGetSymbolAddress((void**)&xhi, g_xhi);
    cudaGetSymbolAddress((void**)&xlo, g_xlo);
    cudaGetSymbolAddress((void**)&h1hi, g_h1hi);
    cudaGetSymbolAddress((void**)&h1lo, g_h1lo);
    cudaGetSymbolAddress((void**)&h2hi, g_h2hi);
    cudaGetSymbolAddress((void**)&h2lo, g_h2lo);
    cudaGetSymbolAddress((void**)&xlr2h, g_xlr2h);
    cudaGetSymbolAddress((void**)&wt1h, g_wt1h);
    cudaGetSymbolAddress((void**)&wt2h, g_wt2h);
    cudaGetSymbolAddress((void**)&wtlh, g_wtlh);
    cudaGetSymbolAddress((void**)&xlr1, g_xlr1);
    cudaGetSymbolAddress((void**)&cb1, g_cb1);
    cudaGetSymbolAddress((void**)&cb2, g_cb2);

    constexpr int SMEM128 = 2 * (2 * 64 * 40 + 128 * 40) * 2;  // 40960 B
    constexpr int SMEM64  = 2 * (2 * 64 * 40 + 64 * 40) * 2;   // 30720 B
    static cudaStream_t s_aux = nullptr;
    static cudaEvent_t e_fork = nullptr, e_csr = nullptr;
    if (!s_aux) {
        cudaFuncSetAttribute((const void*)gemm_f16<128, false>, cudaFuncAttributeMaxDynamicSharedMemorySize, SMEM128);
        cudaFuncSetAttribute((const void*)gemm_f16<128, true>,  cudaFuncAttributeMaxDynamicSharedMemorySize, SMEM128);
        cudaFuncSetAttribute((const void*)gemm_f16<64, false>,  cudaFuncAttributeMaxDynamicSharedMemorySize, SMEM64);
        cudaStreamCreateWithFlags(&s_aux, cudaStreamNonBlocking);
        cudaEventCreateWithFlags(&e_fork, cudaEventDisableTiming);
        cudaEventCreateWithFlags(&e_csr, cudaEventDisableTiming);
    }

    const int MB = (NN + 63) / 64;  // 313

    // #1: fused prep
    k_prep<<<(PREP_TOTAL + 255) / 256, 256>>>(x, Wl1, Wr1, Wl2, Wr2, Wlin, bl1, br1, bl2, br2);

    // fork CSR build onto side stream
    cudaEventRecord(e_fork, 0);
    cudaStreamWaitEvent(s_aux, e_fork, 0);
    k_hist<<<(NE + 255) / 256, 256, 0, s_aux>>>(dst);                 // #2
    k_scan<<<1, 1024, 0, s_aux>>>();                                  // #3

    // #4 (profiled slot): layer-1 GEMM (N=256 = [xl|xr], fp32 out)
    gemm_f16<128, false><<<dim3(2, MB), 256, SMEM128>>>(xhi, xlo, wt1h, cb1, xlr1, NN, 256, 128);

    k_scatter<<<(NE + 255) / 256, 256, 0, s_aux>>>(src, dst);         // #5
    cudaEventRecord(e_csr, s_aux);
    cudaStreamWaitEvent(0, e_csr, 0);

    k_agg1<<<(NN * 32 + 255) / 256, 256>>>(xlr1, att1, bias1, h1hi, h1lo);
    // layer-2 GEMM: fp16 output (halves xlr2 store + agg2 gather traffic)
    gemm_f16<128, true><<<dim3(8, MB), 256, SMEM128>>>(h1hi, h1lo, wt2h, cb2, xlr2h, NN, 1024, 128);
    k_agg2<<<(NN * 2 * 32 + 255) / 256, 256>>>(xlr2h, att2, bias2, h2hi, h2lo);
    gemm_f16<64, false><<<dim3(1, MB), 256, SMEM64>>>(h2hi, h2lo, wtlh, blin, out, NN, 64, 512);
}

// round 13
// speedup vs baseline: 1.1603x; 1.0004x over previous
#include <cuda_runtime.h>
#include <cuda_fp16.h>
#include <cstdint>

#define NN 20000
#define NE 160000

// ---------------- scratch (device globals: allocation-free) ----------------
__device__ __half g_xhi[NN * 128], g_xlo[NN * 128];
__device__ __half g_xlr1h[NN * 256];
__device__ __half g_h1hi[NN * 128], g_h1lo[NN * 128];
__device__ __half g_xlr2h[NN * 1024];
__device__ __half g_h2hi[NN * 512], g_h2lo[NN * 512];
__device__ __half g_wt1h[256 * 128];
__device__ __half g_wt2h[1024 * 128];
__device__ __half g_wtlh[64 * 512];
__device__ float g_cb1[256];
__device__ float g_cb2[1024];
__device__ int g_deg[NN];
__device__ int g_rowptr[NN + 1];
__device__ int g_cursor[NN];
__device__ int g_col[NE];

// ---------------- helpers ----------------
__device__ __forceinline__ uint32_t smem_u32(const void* p) {
    uint32_t a;
    asm("{ .reg .u64 t; cvta.to.shared.u64 t, %1; cvt.u32.u64 %0, t; }" : "=r"(a) : "l"(p));
    return a;
}
__device__ __forceinline__ void cp_async16(uint32_t dst, const void* src, bool pred) {
    int sz = pred ? 16 : 0;
    asm volatile("cp.async.cg.shared.global [%0], [%1], 16, %2;"
                 :: "r"(dst), "l"(src), "r"(sz) : "memory");
}
__device__ __forceinline__ void cp_commit() {
    asm volatile("cp.async.commit_group;" ::: "memory");
}
template <int W> __device__ __forceinline__ void cp_wait() {
    asm volatile("cp.async.wait_group %0;" :: "n"(W) : "memory");
}
__device__ __forceinline__ void split1h(float a, __half& h, __half& l) {
    h = __float2half_rn(a);
    l = __float2half_rn(a - __half2float(h));
}
__device__ __forceinline__ void mma_f16(float* c, const uint32_t* a, const uint32_t* b) {
    asm volatile("mma.sync.aligned.m16n8k16.row.col.f32.f16.f16.f32 "
                 "{%0,%1,%2,%3}, {%4,%5,%6,%7}, {%8,%9}, {%0,%1,%2,%3};"
                 : "+f"(c[0]), "+f"(c[1]), "+f"(c[2]), "+f"(c[3])
                 : "r"(a[0]), "r"(a[1]), "r"(a[2]), "r"(a[3]), "r"(b[0]), "r"(b[1]));
}
__device__ __forceinline__ void ldsm_x4(uint32_t* r, uint32_t addr) {
    asm volatile("ldmatrix.sync.aligned.m8n8.x4.shared.b16 {%0,%1,%2,%3}, [%4];"
                 : "=r"(r[0]), "=r"(r[1]), "=r"(r[2]), "=r"(r[3]) : "r"(addr));
}

// ---------------- fused prep: zero_deg + x split + W transposes + bias -----
__global__ void k_prep(const float* __restrict__ x,
                       const float* __restrict__ Wl1, const float* __restrict__ Wr1,
                       const float* __restrict__ Wl2, const float* __restrict__ Wr2,
                       const float* __restrict__ Wlin,
                       const float* __restrict__ bl1, const float* __restrict__ br1,
                       const float* __restrict__ bl2, const float* __restrict__ br2) {
    const int S0 = NN;
    const int S1 = S0 + NN * 128;
    const int S2 = S1 + 16384;
    const int S3 = S2 + 16384;
    const int S4 = S3 + 65536;
    const int S5 = S4 + 65536;
    const int S6 = S5 + 32768;
    const int S7 = S6 + 1280;
    int i = blockIdx.x * blockDim.x + threadIdx.x;
    if (i < S0) {
        g_deg[i] = 0;
    } else if (i < S1) {
        int j = i - S0;
        __half h, l;
        split1h(x[j], h, l);
        g_xhi[j] = h; g_xlo[j] = l;
    } else if (i < S2) {
        int j = i - S1, k = j >> 7, n = j & 127;
        g_wt1h[n * 128 + k] = __float2half_rn(Wl1[j]);
    } else if (i < S3) {
        int j = i - S2, k = j >> 7, n = j & 127;
        g_wt1h[128 * 128 + n * 128 + k] = __float2half_rn(Wr1[j]);
    } else if (i < S4) {
        int j = i - S3, k = j >> 9, n = j & 511;
        g_wt2h[n * 128 + k] = __float2half_rn(Wl2[j]);
    } else if (i < S5) {
        int j = i - S4, k = j >> 9, n = j & 511;
        g_wt2h[512 * 128 + n * 128 + k] = __float2half_rn(Wr2[j]);
    } else if (i < S6) {
        int j = i - S5, k = j >> 6, n = j & 63;
        g_wtlh[n * 512 + k] = __float2half_rn(Wlin[j]);
    } else if (i < S7) {
        int j = i - S6;
        if (j < 256) g_cb1[j] = (j < 128) ? bl1[j] : br1[j - 128];
        else {
            int b = j - 256;
            g_cb2[b] = (b < 512) ? bl2[b] : br2[b - 512];
        }
    }
}
#define PREP_TOTAL (NN + NN * 128 + 16384 * 2 + 65536 * 2 + 32768 + 1280)

// ---------------- CSR build (counting sort by dst) ----------------
__global__ void k_hist(const int* __restrict__ dst) {
    int e = blockIdx.x * blockDim.x + threadIdx.x;
    if (e < NE) atomicAdd(&g_deg[dst[e]], 1);
}
__global__ void k_scan() {
    __shared__ int s[1024];
    const int CH = (NN + 1023) / 1024;
    int t = threadIdx.x;
    int start = t * CH;
    int end = start + CH < NN ? start + CH : NN;
    int sum = 0;
    for (int i = start; i < end; i++) sum += g_deg[i];
    s[t] = sum;
    __syncthreads();
    for (int off = 1; off < 1024; off <<= 1) {
        int v = (t >= off) ? s[t - off] : 0;
        __syncthreads();
        s[t] += v;
        __syncthreads();
    }
    int run = (t == 0) ? 0 : s[t - 1];
    for (int i = start; i < end; i++) {
        g_rowptr[i] = run;
        g_cursor[i] = run;
        run += g_deg[i];
    }
    if (t == 1023) g_rowptr[NN] = s[1023];
}
__global__ void k_scatter(const int* __restrict__ src, const int* __restrict__ dst) {
    int e = blockIdx.x * blockDim.x + threadIdx.x;
    if (e < NE) {
        int d = dst[e];
        int pos = atomicAdd(&g_cursor[d], 1);
        g_col[pos] = src[e];
    }
}

// ---------------- pipelined fp16 2-MMA split GEMM (R9 2-stage) ------------
template <int BN, bool HOUT>
__global__ void __launch_bounds__(256, 3)
gemm_f16(const __half* __restrict__ Ahi, const __half* __restrict__ Alo,
         const __half* __restrict__ Bh, const float* __restrict__ bias,
         void* __restrict__ Cv, int M, int N, int K) {
    constexpr int BM = 64;
    constexpr int BK = 32;
    constexpr int STR = 40;
    constexpr int ASZ = BM * STR;
    constexpr int BSZ = BN * STR;
    constexpr int STAGE = 2 * ASZ + BSZ;
    constexpr int NT = BN / 32;
    extern __shared__ __half sm[];

    const int tid = threadIdx.x;
    const int wid = tid >> 5;
    const int lane = tid & 31;
    const int wm = wid & 1;
    const int wn = wid >> 1;
    const int gid = lane >> 2;
    const int tig = lane & 3;
    const int m0 = blockIdx.y * BM;
    const int n0 = blockIdx.x * BN;
    const int nk = K / BK;

    const int a_row = wm * 32 + (lane & 7) + ((lane >> 3) & 1) * 8;
    const int a_koff = (lane & 16) >> 1;
    const int b_row = wn * (NT * 8) + (lane & 7) + ((lane & 16) >> 1);
    const int b_koff = lane & 8;

    float c[2][NT][4];
#pragma unroll
    for (int mt = 0; mt < 2; mt++)
#pragma unroll
        for (int nt = 0; nt < NT; nt++)
#pragma unroll
            for (int r = 0; r < 4; r++) c[mt][nt][r] = 0.f;

    auto load_stage = [&](int kc, int s) {
        const int k0 = kc * BK;
        __half* base = sm + s * STAGE;
        {
            int row = tid >> 2, ch = tid & 3;
            int gm = m0 + row;
            bool p = gm < M;
            int gmc = p ? gm : (M - 1);
            size_t goff = (size_t)gmc * K + k0 + ch * 8;
            uint32_t d = smem_u32(base + row * STR + ch * 8);
            cp_async16(d, Ahi + goff, p);
            cp_async16(d + ASZ * 2, Alo + goff, p);
        }
#pragma unroll
        for (int j = 0; j < BN / 64; j++) {
            int i = tid + j * 256;
            int row = i >> 2, ch = i & 3;
            size_t goff = (size_t)(n0 + row) * K + k0 + ch * 8;
            uint32_t d = smem_u32(base + 2 * ASZ + row * STR + ch * 8);
            cp_async16(d, Bh + goff, true);
        }
    };

    load_stage(0, 0);
    cp_commit();

    for (int kc = 0; kc < nk; kc++) {
        const int s = kc & 1;
        if (kc + 1 < nk) {
            load_stage(kc + 1, s ^ 1);
            cp_commit();
            cp_wait<1>();
        } else {
            cp_wait<0>();
        }
        __syncthreads();

        const uint32_t stg = smem_u32(sm + s * STAGE);
        const uint32_t ah_base = stg + (a_row * STR + a_koff) * 2;
        const uint32_t al_base = ah_base + ASZ * 2;
        const uint32_t bh_base = stg + 2 * ASZ * 2 + (b_row * STR + b_koff) * 2;

#pragma unroll
        for (int kb = 0; kb < BK; kb += 16) {
            uint32_t bfh[NT][2];
#pragma unroll
            for (int p = 0; p < NT / 2; p++) {
                uint32_t off = (p * 16 * STR + kb) * 2;
                ldsm_x4(&bfh[2 * p][0], bh_base + off);
            }
#pragma unroll
            for (int mt = 0; mt < 2; mt++) {
                uint32_t afh[4], afl[4];
                uint32_t off = (mt * 16 * STR + kb) * 2;
                ldsm_x4(afh, ah_base + off);
                ldsm_x4(afl, al_base + off);
#pragma unroll
                for (int nt = 0; nt < NT; nt++) {
                    mma_f16(c[mt][nt], afh, bfh[nt]);
                    mma_f16(c[mt][nt], afl, bfh[nt]);
                }
            }
        }
        __syncthreads();
    }

#pragma unroll
    for (int mt = 0; mt < 2; mt++) {
        int r0 = m0 + wm * 32 + mt * 16 + gid;
#pragma unroll
        for (int nt = 0; nt < NT; nt++) {
            int col = n0 + wn * (NT * 8) + nt * 8 + tig * 2;
            float b0 = bias[col], b1 = bias[col + 1];
            if (HOUT) {
                __half* Ch = (__half*)Cv;
                if (r0 < M)
                    *reinterpret_cast<__half2*>(Ch + (size_t)r0 * N + col) =
                        __floats2half2_rn(c[mt][nt][0] + b0, c[mt][nt][1] + b1);
                if (r0 + 8 < M)
                    *reinterpret_cast<__half2*>(Ch + (size_t)(r0 + 8) * N + col) =
                        __floats2half2_rn(c[mt][nt][2] + b0, c[mt][nt][3] + b1);
            } else {
                float* Cf = (float*)Cv;
                if (r0 < M) {
                    float2 v0 = make_float2(c[mt][nt][0] + b0, c[mt][nt][1] + b1);
                    *reinterpret_cast<float2*>(Cf + (size_t)r0 * N + col) = v0;
                }
                if (r0 + 8 < M) {
                    float2 v1 = make_float2(c[mt][nt][2] + b0, c[mt][nt][3] + b1);
                    *reinterpret_cast<float2*>(Cf + (size_t)(r0 + 8) * N + col) = v1;
                }
            }
        }
    }
}

// ---------------- layer-1 agg (fp16 xlr storage, D=128, NWPN=1) ------------
__global__ void __launch_bounds__(256, 3)
k_agg1(const __half* __restrict__ xlrh,
       const float* __restrict__ att, const float* __restrict__ bias,
       __half* __restrict__ ohi, __half* __restrict__ olo) {
    constexpr int D = 128, SR = 256, XO = 128;
    constexpr int CPL = 4;

    int warp = (blockIdx.x * blockDim.x + threadIdx.x) >> 5;
    int lane = threadIdx.x & 31;
    if (warp >= NN) return;
    const int node = warp;
    const int base = lane * CPL;

    float attv[CPL], xrv[CPL];
    {
        float4 a4 = *reinterpret_cast<const float4*>(att + base);
        attv[0] = a4.x; attv[1] = a4.y; attv[2] = a4.z; attv[3] = a4.w;
        uint2 r = *reinterpret_cast<const uint2*>(xlrh + (size_t)node * SR + XO + base);
        const __half2* rp = reinterpret_cast<const __half2*>(&r);
        float2 f0 = __half22float2(rp[0]);
        float2 f1 = __half22float2(rp[1]);
        xrv[0] = f0.x; xrv[1] = f0.y; xrv[2] = f1.x; xrv[3] = f1.y;
    }

    float m = -3.402823466e38f;
    float ssum = 0.f;
    float acc[CPL];
#pragma unroll
    for (int c = 0; c < CPL; c++) acc[c] = 0.f;

    const int rs = g_rowptr[node];
    const int re = g_rowptr[node + 1];

    if (rs < re) {
        int s = g_col[rs];
        uint2 cur = *reinterpret_cast<const uint2*>(xlrh + (size_t)s * SR + base);
        for (int p = rs; p < re; p++) {
            int sn = (p + 1 < re) ? g_col[p + 1] : s;
            uint2 nxt = *reinterpret_cast<const uint2*>(xlrh + (size_t)sn * SR + base);

            float xlv[CPL];
            const __half2* cp = reinterpret_cast<const __half2*>(&cur);
            float2 f0 = __half22float2(cp[0]);
            float2 f1 = __half22float2(cp[1]);
            xlv[0] = f0.x; xlv[1] = f0.y; xlv[2] = f1.x; xlv[3] = f1.y;

            float partial = 0.f;
#pragma unroll
            for (int c = 0; c < CPL; c++) {
                float e = xlv[c] + xrv[c];
                e = (e >= 0.f) ? e : 0.2f * e;
                partial = fmaf(attv[c], e, partial);
            }
            partial += __shfl_xor_sync(0xffffffffu, partial, 1);
            partial += __shfl_xor_sync(0xffffffffu, partial, 2);
            partial += __shfl_xor_sync(0xffffffffu, partial, 4);

            float mnew = fmaxf(m, partial);
            float fac = __expf(m - mnew);
            float w = __expf(partial - mnew);
            ssum = ssum * fac + w;
#pragma unroll
            for (int c = 0; c < CPL; c++) acc[c] = fmaf(acc[c], fac, w * xlv[c]);
            m = mnew;
            cur = nxt;
        }
    }

    float inv = (ssum > 0.f) ? (1.f / ssum) : 0.f;
#pragma unroll
    for (int j = 0; j < CPL / 2; j++) {
        float v0 = fmaxf(fmaf(acc[2 * j], inv, bias[base + 2 * j]), 0.f);
        float v1 = fmaxf(fmaf(acc[2 * j + 1], inv, bias[base + 2 * j + 1]), 0.f);
        __half h0, l0, h1, l1;
        split1h(v0, h0, l0);
        split1h(v1, h1, l1);
        *reinterpret_cast<__half2*>(ohi + (size_t)node * D + base + 2 * j) = __halves2half2(h0, h1);
        *reinterpret_cast<__half2*>(olo + (size_t)node * D + base + 2 * j) = __halves2half2(l0, l1);
    }
}

// ---------------- layer-2 agg (fp16 xlr storage, D=512, NWPN=2) ------------
__global__ void __launch_bounds__(256, 3)
k_agg2(const __half* __restrict__ xlrh,
       const float* __restrict__ att, const float* __restrict__ bias,
       __half* __restrict__ ohi, __half* __restrict__ olo) {
    constexpr int SR = 1024, XO = 512;
    constexpr int CPL = 8;

    int gw = (blockIdx.x * blockDim.x + threadIdx.x) >> 5;
    int lane = threadIdx.x & 31;
    int node = gw >> 1;
    int part = gw & 1;
    if (node >= NN) return;
    const int base = part * 256 + lane * CPL;

    float attv[CPL], xrv[CPL];
    {
        float4 a0 = *reinterpret_cast<const float4*>(att + base);
        float4 a1 = *reinterpret_cast<const float4*>(att + base + 4);
        attv[0] = a0.x; attv[1] = a0.y; attv[2] = a0.z; attv[3] = a0.w;
        attv[4] = a1.x; attv[5] = a1.y; attv[6] = a1.z; attv[7] = a1.w;
        uint4 r = *reinterpret_cast<const uint4*>(xlrh + (size_t)node * SR + XO + base);
        const __half2* rp = reinterpret_cast<const __half2*>(&r);
#pragma unroll
        for (int j = 0; j < 4; j++) {
            float2 f = __half22float2(rp[j]);
            xrv[2 * j] = f.x; xrv[2 * j + 1] = f.y;
        }
    }

    float m = -3.402823466e38f;
    float ssum = 0.f;
    float acc[CPL];
#pragma unroll
    for (int c = 0; c < CPL; c++) acc[c] = 0.f;

    const int rs = g_rowptr[node];
    const int re = g_rowptr[node + 1];

    if (rs < re) {
        int s = g_col[rs];
        uint4 cur = *reinterpret_cast<const uint4*>(xlrh + (size_t)s * SR + base);
        for (int p = rs; p < re; p++) {
            int sn = (p + 1 < re) ? g_col[p + 1] : s;
            uint4 nxt = *reinterpret_cast<const uint4*>(xlrh + (size_t)sn * SR + base);

            float xlv[CPL];
            const __half2* cp = reinterpret_cast<const __half2*>(&cur);
#pragma unroll
            for (int j = 0; j < 4; j++) {
                float2 f = __half22float2(cp[j]);
                xlv[2 * j] = f.x; xlv[2 * j + 1] = f.y;
            }
            float partial = 0.f;
#pragma unroll
            for (int c = 0; c < CPL; c++) {
                float e = xlv[c] + xrv[c];
                e = (e >= 0.f) ? e : 0.2f * e;
                partial = fmaf(attv[c], e, partial);
            }
            partial += __shfl_xor_sync(0xffffffffu, partial, 1);
            partial += __shfl_xor_sync(0xffffffffu, partial, 2);
            partial += __shfl_xor_sync(0xffffffffu, partial, 4);
            partial += __shfl_xor_sync(0xffffffffu, partial, 8);

            float mnew = fmaxf(m, partial);
            float fac = __expf(m - mnew);
            float w = __expf(partial - mnew);
            ssum = ssum * fac + w;
#pragma unroll
            for (int c = 0; c < CPL; c++) acc[c] = fmaf(acc[c], fac, w * xlv[c]);
            m = mnew;
            cur = nxt;
        }
    }

    float inv = (ssum > 0.f) ? (1.f / ssum) : 0.f;
#pragma unroll
    for (int j = 0; j < CPL / 2; j++) {
        float v0 = fmaxf(fmaf(acc[2 * j], inv, bias[base + 2 * j]), 0.f);
        float v1 = fmaxf(fmaf(acc[2 * j + 1], inv, bias[base + 2 * j + 1]), 0.f);
        __half h0, l0, h1, l1;
        split1h(v0, h0, l0);
        split1h(v1, h1, l1);
        *reinterpret_cast<__half2*>(ohi + (size_t)node * 512 + base + 2 * j) = __halves2half2(h0, h1);
        *reinterpret_cast<__half2*>(olo + (size_t)node * 512 + base + 2 * j) = __halves2half2(l0, l1);
    }
}

// ---------------- launch ----------------
extern "C" void kernel_launch(void* const* d_in, const int* in_sizes, int n_in,
                              void* d_out, int out_size) {
    (void)in_sizes; (void)n_in; (void)out_size;
    const float* x     = (const float*)d_in[0];
    const int*   ei    = (const int*)  d_in[1];
    const float* Wl1   = (const float*)d_in[3];
    const float* bl1   = (const float*)d_in[4];
    const float* Wr1   = (const float*)d_in[5];
    const float* br1   = (const float*)d_in[6];
    const float* att1  = (const float*)d_in[7];
    const float* bias1 = (const float*)d_in[8];
    const float* Wl2   = (const float*)d_in[9];
    const float* bl2   = (const float*)d_in[10];
    const float* Wr2   = (const float*)d_in[11];
    const float* br2   = (const float*)d_in[12];
    const float* att2  = (const float*)d_in[13];
    const float* bias2 = (const float*)d_in[14];
    const float* Wlin  = (const float*)d_in[15];
    const float* blin  = (const float*)d_in[16];
    float* out = (float*)d_out;

    const int* src = ei;
    const int* dst = ei + NE;

    __half *xhi, *xlo, *h1hi, *h1lo, *h2hi, *h2lo, *xlr1h, *xlr2h;
    __half *wt1h, *wt2h, *wtlh;
    float *cb1, *cb2;
    cudaGetSymbolAddress((void**)&xhi, g_xhi);
    cudaGetSymbolAddress((void**)&xlo, g_xlo);
    cudaGetSymbolAddress((void**)&h1hi, g_h1hi);
    cudaGetSymbolAddress((void**)&h1lo, g_h1lo);
    cudaGetSymbolAddress((void**)&h2hi, g_h2hi);
    cudaGetSymbolAddress((void**)&h2lo, g_h2lo);
    cudaGetSymbolAddress((void**)&xlr1h, g_xlr1h);
    cudaGetSymbolAddress((void**)&xlr2h, g_xlr2h);
    cudaGetSymbolAddress((void**)&wt1h, g_wt1h);
    cudaGetSymbolAddress((void**)&wt2h, g_wt2h);
    cudaGetSymbolAddress((void**)&wtlh, g_wtlh);
    cudaGetSymbolAddress((void**)&cb1, g_cb1);
    cudaGetSymbolAddress((void**)&cb2, g_cb2);

    constexpr int SMEM128 = 2 * (2 * 64 * 40 + 128 * 40) * 2;  // 40960 B
    constexpr int SMEM64  = 2 * (2 * 64 * 40 + 64 * 40) * 2;   // 30720 B
    static cudaStream_t s_aux = nullptr;
    static cudaEvent_t e_fork = nullptr, e_csr = nullptr;
    if (!s_aux) {
        cudaFuncSetAttribute((const void*)gemm_f16<128, true>,  cudaFuncAttributeMaxDynamicSharedMemorySize, SMEM128);
        cudaFuncSetAttribute((const void*)gemm_f16<64, false>,  cudaFuncAttributeMaxDynamicSharedMemorySize, SMEM64);
        cudaStreamCreateWithFlags(&s_aux, cudaStreamNonBlocking);
        cudaEventCreateWithFlags(&e_fork, cudaEventDisableTiming);
        cudaEventCreateWithFlags(&e_csr, cudaEventDisableTiming);
    }

    const int MB = (NN + 63) / 64;  // 313

    // #1: fused prep
    k_prep<<<(PREP_TOTAL + 255) / 256, 256>>>(x, Wl1, Wr1, Wl2, Wr2, Wlin, bl1, br1, bl2, br2);

    // fork CSR build onto side stream
    cudaEventRecord(e_fork, 0);
    cudaStreamWaitEvent(s_aux, e_fork, 0);
    k_hist<<<(NE + 255) / 256, 256, 0, s_aux>>>(dst);                 // #2
    k_scan<<<1, 1024, 0, s_aux>>>();                                  // #3

    // #4 (profiled slot): layer-1 GEMM (N=256 = [xl|xr], fp16 out)
    gemm_f16<128, true><<<dim3(2, MB), 256, SMEM128>>>(xhi, xlo, wt1h, cb1, xlr1h, NN, 256, 128);

    k_scatter<<<(NE + 255) / 256, 256, 0, s_aux>>>(src, dst);         // #5
    cudaEventRecord(e_csr, s_aux);
    cudaStreamWaitEvent(0, e_csr, 0);

    k_agg1<<<(NN * 32 + 255) / 256, 256>>>(xlr1h, att1, bias1, h1hi, h1lo);
    gemm_f16<128, true><<<dim3(8, MB), 256, SMEM128>>>(h1hi, h1lo, wt2h, cb2, xlr2h, NN, 1024, 128);
    k_agg2<<<(NN * 2 * 32 + 255) / 256, 256>>>(xlr2h, att2, bias2, h2hi, h2lo);
    gemm_f16<64, false><<<dim3(1, MB), 256, SMEM64>>>(h2hi, h2lo, wtlh, blin, out, NN, 64, 512);
}

// round 14
// speedup vs baseline: 1.2297x; 1.0599x over previous
#include <cuda_runtime.h>
#include <cuda_fp16.h>
#include <cstdint>

#define NN 20000
#define NE 160000

// ---------------- scratch (device globals: allocation-free) ----------------
__device__ __half g_xhi[NN * 128], g_xlo[NN * 128];
__device__ __half g_xlr1h[NN * 256];
__device__ __half g_h1h[NN * 128];
__device__ __half g_xlr2h[NN * 1024];
__device__ __half g_h2hi[NN * 512], g_h2lo[NN * 512];
__device__ __half g_wt1h[256 * 128];
__device__ __half g_wt2h[1024 * 128];
__device__ __half g_wtlh[64 * 512];
__device__ float g_cb1[256];
__device__ float g_cb2[1024];
__device__ int g_deg[NN];
__device__ int g_rowptr[NN + 1];
__device__ int g_cursor[NN];
__device__ int g_col[NE];

// ---------------- helpers ----------------
__device__ __forceinline__ uint32_t smem_u32(const void* p) {
    uint32_t a;
    asm("{ .reg .u64 t; cvta.to.shared.u64 t, %1; cvt.u32.u64 %0, t; }" : "=r"(a) : "l"(p));
    return a;
}
__device__ __forceinline__ void cp_async16(uint32_t dst, const void* src, bool pred) {
    int sz = pred ? 16 : 0;
    asm volatile("cp.async.cg.shared.global [%0], [%1], 16, %2;"
                 :: "r"(dst), "l"(src), "r"(sz) : "memory");
}
__device__ __forceinline__ void cp_commit() {
    asm volatile("cp.async.commit_group;" ::: "memory");
}
template <int W> __device__ __forceinline__ void cp_wait() {
    asm volatile("cp.async.wait_group %0;" :: "n"(W) : "memory");
}
__device__ __forceinline__ void split1h(float a, __half& h, __half& l) {
    h = __float2half_rn(a);
    l = __float2half_rn(a - __half2float(h));
}
__device__ __forceinline__ void mma_f16(float* c, const uint32_t* a, const uint32_t* b) {
    asm volatile("mma.sync.aligned.m16n8k16.row.col.f32.f16.f16.f32 "
                 "{%0,%1,%2,%3}, {%4,%5,%6,%7}, {%8,%9}, {%0,%1,%2,%3};"
                 : "+f"(c[0]), "+f"(c[1]), "+f"(c[2]), "+f"(c[3])
                 : "r"(a[0]), "r"(a[1]), "r"(a[2]), "r"(a[3]), "r"(b[0]), "r"(b[1]));
}
__device__ __forceinline__ void ldsm_x4(uint32_t* r, uint32_t addr) {
    asm volatile("ldmatrix.sync.aligned.m8n8.x4.shared.b16 {%0,%1,%2,%3}, [%4];"
                 : "=r"(r[0]), "=r"(r[1]), "=r"(r[2]), "=r"(r[3]) : "r"(addr));
}

// ---------------- fused prep: zero_deg + x split + W transposes + bias -----
__global__ void k_prep(const float* __restrict__ x,
                       const float* __restrict__ Wl1, const float* __restrict__ Wr1,
                       const float* __restrict__ Wl2, const float* __restrict__ Wr2,
                       const float* __restrict__ Wlin,
                       const float* __restrict__ bl1, const float* __restrict__ br1,
                       const float* __restrict__ bl2, const float* __restrict__ br2) {
    const int S0 = NN;
    const int S1 = S0 + NN * 128;
    const int S2 = S1 + 16384;
    const int S3 = S2 + 16384;
    const int S4 = S3 + 65536;
    const int S5 = S4 + 65536;
    const int S6 = S5 + 32768;
    const int S7 = S6 + 1280;
    int i = blockIdx.x * blockDim.x + threadIdx.x;
    if (i < S0) {
        g_deg[i] = 0;
    } else if (i < S1) {
        int j = i - S0;
        __half h, l;
        split1h(x[j], h, l);
        g_xhi[j] = h; g_xlo[j] = l;
    } else if (i < S2) {
        int j = i - S1, k = j >> 7, n = j & 127;
        g_wt1h[n * 128 + k] = __float2half_rn(Wl1[j]);
    } else if (i < S3) {
        int j = i - S2, k = j >> 7, n = j & 127;
        g_wt1h[128 * 128 + n * 128 + k] = __float2half_rn(Wr1[j]);
    } else if (i < S4) {
        int j = i - S3, k = j >> 9, n = j & 511;
        g_wt2h[n * 128 + k] = __float2half_rn(Wl2[j]);
    } else if (i < S5) {
        int j = i - S4, k = j >> 9, n = j & 511;
        g_wt2h[512 * 128 + n * 128 + k] = __float2half_rn(Wr2[j]);
    } else if (i < S6) {
        int j = i - S5, k = j >> 6, n = j & 63;
        g_wtlh[n * 512 + k] = __float2half_rn(Wlin[j]);
    } else if (i < S7) {
        int j = i - S6;
        if (j < 256) g_cb1[j] = (j < 128) ? bl1[j] : br1[j - 128];
        else {
            int b = j - 256;
            g_cb2[b] = (b < 512) ? bl2[b] : br2[b - 512];
        }
    }
}
#define PREP_TOTAL (NN + NN * 128 + 16384 * 2 + 65536 * 2 + 32768 + 1280)

// ---------------- CSR build (counting sort by dst) ----------------
__global__ void k_hist(const int* __restrict__ dst) {
    int e = blockIdx.x * blockDim.x + threadIdx.x;
    if (e < NE) atomicAdd(&g_deg[dst[e]], 1);
}
__global__ void k_scan() {
    __shared__ int s[1024];
    const int CH = (NN + 1023) / 1024;
    int t = threadIdx.x;
    int start = t * CH;
    int end = start + CH < NN ? start + CH : NN;
    int sum = 0;
    for (int i = start; i < end; i++) sum += g_deg[i];
    s[t] = sum;
    __syncthreads();
    for (int off = 1; off < 1024; off <<= 1) {
        int v = (t >= off) ? s[t - off] : 0;
        __syncthreads();
        s[t] += v;
        __syncthreads();
    }
    int run = (t == 0) ? 0 : s[t - 1];
    for (int i = start; i < end; i++) {
        g_rowptr[i] = run;
        g_cursor[i] = run;
        run += g_deg[i];
    }
    if (t == 1023) g_rowptr[NN] = s[1023];
}
__global__ void k_scatter(const int* __restrict__ src, const int* __restrict__ dst) {
    int e = blockIdx.x * blockDim.x + threadIdx.x;
    if (e < NE) {
        int d = dst[e];
        int pos = atomicAdd(&g_cursor[d], 1);
        g_col[pos] = src[e];
    }
}

// ---------------- pipelined fp16 GEMM (optional A-split, R9 2-stage) ------
// ASPLIT=1: C = (Ah+Al) @ Bh^T + bias.  ASPLIT=0: C = Ah @ Bh^T + bias.
template <int BN, bool HOUT, bool ASPLIT>
__global__ void __launch_bounds__(256, 3)
gemm_f16(const __half* __restrict__ Ahi, const __half* __restrict__ Alo,
         const __half* __restrict__ Bh, const float* __restrict__ bias,
         void* __restrict__ Cv, int M, int N, int K) {
    constexpr int BM = 64;
    constexpr int BK = 32;
    constexpr int STR = 40;
    constexpr int ASZ = BM * STR;
    constexpr int BSZ = BN * STR;
    constexpr int NA = ASPLIT ? 2 : 1;
    constexpr int STAGE = NA * ASZ + BSZ;
    constexpr int NT = BN / 32;
    extern __shared__ __half sm[];

    const int tid = threadIdx.x;
    const int wid = tid >> 5;
    const int lane = tid & 31;
    const int wm = wid & 1;
    const int wn = wid >> 1;
    const int gid = lane >> 2;
    const int tig = lane & 3;
    const int m0 = blockIdx.y * BM;
    const int n0 = blockIdx.x * BN;
    const int nk = K / BK;

    const int a_row = wm * 32 + (lane & 7) + ((lane >> 3) & 1) * 8;
    const int a_koff = (lane & 16) >> 1;
    const int b_row = wn * (NT * 8) + (lane & 7) + ((lane & 16) >> 1);
    const int b_koff = lane & 8;

    float c[2][NT][4];
#pragma unroll
    for (int mt = 0; mt < 2; mt++)
#pragma unroll
        for (int nt = 0; nt < NT; nt++)
#pragma unroll
            for (int r = 0; r < 4; r++) c[mt][nt][r] = 0.f;

    auto load_stage = [&](int kc, int s) {
        const int k0 = kc * BK;
        __half* base = sm + s * STAGE;
        {
            int row = tid >> 2, ch = tid & 3;
            int gm = m0 + row;
            bool p = gm < M;
            int gmc = p ? gm : (M - 1);
            size_t goff = (size_t)gmc * K + k0 + ch * 8;
            uint32_t d = smem_u32(base + row * STR + ch * 8);
            cp_async16(d, Ahi + goff, p);
            if (ASPLIT) cp_async16(d + ASZ * 2, Alo + goff, p);
        }
#pragma unroll
        for (int j = 0; j < BN / 64; j++) {
            int i = tid + j * 256;
            int row = i >> 2, ch = i & 3;
            size_t goff = (size_t)(n0 + row) * K + k0 + ch * 8;
            uint32_t d = smem_u32(base + NA * ASZ + row * STR + ch * 8);
            cp_async16(d, Bh + goff, true);
        }
    };

    load_stage(0, 0);
    cp_commit();

    for (int kc = 0; kc < nk; kc++) {
        const int s = kc & 1;
        if (kc + 1 < nk) {
            load_stage(kc + 1, s ^ 1);
            cp_commit();
            cp_wait<1>();
        } else {
            cp_wait<0>();
        }
        __syncthreads();

        const uint32_t stg = smem_u32(sm + s * STAGE);
        const uint32_t ah_base = stg + (a_row * STR + a_koff) * 2;
        const uint32_t al_base = ah_base + ASZ * 2;
        const uint32_t bh_base = stg + NA * ASZ * 2 + (b_row * STR + b_koff) * 2;

#pragma unroll
        for (int kb = 0; kb < BK; kb += 16) {
            uint32_t bfh[NT][2];
#pragma unroll
            for (int p = 0; p < NT / 2; p++) {
                uint32_t off = (p * 16 * STR + kb) * 2;
                ldsm_x4(&bfh[2 * p][0], bh_base + off);
            }
#pragma unroll
            for (int mt = 0; mt < 2; mt++) {
                uint32_t afh[4], afl[4];
                uint32_t off = (mt * 16 * STR + kb) * 2;
                ldsm_x4(afh, ah_base + off);
                if (ASPLIT) ldsm_x4(afl, al_base + off);
#pragma unroll
                for (int nt = 0; nt < NT; nt++) {
                    mma_f16(c[mt][nt], afh, bfh[nt]);
                    if (ASPLIT) mma_f16(c[mt][nt], afl, bfh[nt]);
                }
            }
        }
        __syncthreads();
    }

#pragma unroll
    for (int mt = 0; mt < 2; mt++) {
        int r0 = m0 + wm * 32 + mt * 16 + gid;
#pragma unroll
        for (int nt = 0; nt < NT; nt++) {
            int col = n0 + wn * (NT * 8) + nt * 8 + tig * 2;
            float b0 = bias[col], b1 = bias[col + 1];
            if (HOUT) {
                __half* Ch = (__half*)Cv;
                if (r0 < M)
                    *reinterpret_cast<__half2*>(Ch + (size_t)r0 * N + col) =
                        __floats2half2_rn(c[mt][nt][0] + b0, c[mt][nt][1] + b1);
                if (r0 + 8 < M)
                    *reinterpret_cast<__half2*>(Ch + (size_t)(r0 + 8) * N + col) =
                        __floats2half2_rn(c[mt][nt][2] + b0, c[mt][nt][3] + b1);
            } else {
                float* Cf = (float*)Cv;
                if (r0 < M) {
                    float2 v0 = make_float2(c[mt][nt][0] + b0, c[mt][nt][1] + b1);
                    *reinterpret_cast<float2*>(Cf + (size_t)r0 * N + col) = v0;
                }
                if (r0 + 8 < M) {
                    float2 v1 = make_float2(c[mt][nt][2] + b0, c[mt][nt][3] + b1);
                    *reinterpret_cast<float2*>(Cf + (size_t)(r0 + 8) * N + col) = v1;
                }
            }
        }
    }
}

// ---------------- layer-1 agg (fp16 in, single-fp16 h1 out) ----------------
__global__ void __launch_bounds__(256, 3)
k_agg1(const __half* __restrict__ xlrh,
       const float* __restrict__ att, const float* __restrict__ bias,
       __half* __restrict__ oh) {
    constexpr int D = 128, SR = 256, XO = 128;
    constexpr int CPL = 4;

    int warp = (blockIdx.x * blockDim.x + threadIdx.x) >> 5;
    int lane = threadIdx.x & 31;
    if (warp >= NN) return;
    const int node = warp;
    const int base = lane * CPL;

    float attv[CPL], xrv[CPL];
    {
        float4 a4 = *reinterpret_cast<const float4*>(att + base);
        attv[0] = a4.x; attv[1] = a4.y; attv[2] = a4.z; attv[3] = a4.w;
        uint2 r = *reinterpret_cast<const uint2*>(xlrh + (size_t)node * SR + XO + base);
        const __half2* rp = reinterpret_cast<const __half2*>(&r);
        float2 f0 = __half22float2(rp[0]);
        float2 f1 = __half22float2(rp[1]);
        xrv[0] = f0.x; xrv[1] = f0.y; xrv[2] = f1.x; xrv[3] = f1.y;
    }

    float m = -3.402823466e38f;
    float ssum = 0.f;
    float acc[CPL];
#pragma unroll
    for (int c = 0; c < CPL; c++) acc[c] = 0.f;

    const int rs = g_rowptr[node];
    const int re = g_rowptr[node + 1];

    if (rs < re) {
        int s = g_col[rs];
        uint2 cur = *reinterpret_cast<const uint2*>(xlrh + (size_t)s * SR + base);
        for (int p = rs; p < re; p++) {
            int sn = (p + 1 < re) ? g_col[p + 1] : s;
            uint2 nxt = *reinterpret_cast<const uint2*>(xlrh + (size_t)sn * SR + base);

            float xlv[CPL];
            const __half2* cp = reinterpret_cast<const __half2*>(&cur);
            float2 f0 = __half22float2(cp[0]);
            float2 f1 = __half22float2(cp[1]);
            xlv[0] = f0.x; xlv[1] = f0.y; xlv[2] = f1.x; xlv[3] = f1.y;

            float partial = 0.f;
#pragma unroll
            for (int c = 0; c < CPL; c++) {
                float e = xlv[c] + xrv[c];
                e = (e >= 0.f) ? e : 0.2f * e;
                partial = fmaf(attv[c], e, partial);
            }
            partial += __shfl_xor_sync(0xffffffffu, partial, 1);
            partial += __shfl_xor_sync(0xffffffffu, partial, 2);
            partial += __shfl_xor_sync(0xffffffffu, partial, 4);

            float mnew = fmaxf(m, partial);
            float fac = __expf(m - mnew);
            float w = __expf(partial - mnew);
            ssum = ssum * fac + w;
#pragma unroll
            for (int c = 0; c < CPL; c++) acc[c] = fmaf(acc[c], fac, w * xlv[c]);
            m = mnew;
            cur = nxt;
        }
    }

    float inv = (ssum > 0.f) ? (1.f / ssum) : 0.f;
#pragma unroll
    for (int j = 0; j < CPL / 2; j++) {
        float v0 = fmaxf(fmaf(acc[2 * j], inv, bias[base + 2 * j]), 0.f);
        float v1 = fmaxf(fmaf(acc[2 * j + 1], inv, bias[base + 2 * j + 1]), 0.f);
        *reinterpret_cast<__half2*>(oh + (size_t)node * D + base + 2 * j) = __floats2half2_rn(v0, v1);
    }
}

// ---------------- layer-2 agg (fp16 in, split h2 out; unchanged R12) -------
__global__ void __launch_bounds__(256, 3)
k_agg2(const __half* __restrict__ xlrh,
       const float* __restrict__ att, const float* __restrict__ bias,
       __half* __restrict__ ohi, __half* __restrict__ olo) {
    constexpr int SR = 1024, XO = 512;
    constexpr int CPL = 8;

    int gw = (blockIdx.x * blockDim.x + threadIdx.x) >> 5;
    int lane = threadIdx.x & 31;
    int node = gw >> 1;
    int part = gw & 1;
    if (node >= NN) return;
    const int base = part * 256 + lane * CPL;

    float attv[CPL], xrv[CPL];
    {
        float4 a0 = *reinterpret_cast<const float4*>(att + base);
        float4 a1 = *reinterpret_cast<const float4*>(att + base + 4);
        attv[0] = a0.x; attv[1] = a0.y; attv[2] = a0.z; attv[3] = a0.w;
        attv[4] = a1.x; attv[5] = a1.y; attv[6] = a1.z; attv[7] = a1.w;
        uint4 r = *reinterpret_cast<const uint4*>(xlrh + (size_t)node * SR + XO + base);
        const __half2* rp = reinterpret_cast<const __half2*>(&r);
#pragma unroll
        for (int j = 0; j < 4; j++) {
            float2 f = __half22float2(rp[j]);
            xrv[2 * j] = f.x; xrv[2 * j + 1] = f.y;
        }
    }

    float m = -3.402823466e38f;
    float ssum = 0.f;
    float acc[CPL];
#pragma unroll
    for (int c = 0; c < CPL; c++) acc[c] = 0.f;

    const int rs = g_rowptr[node];
    const int re = g_rowptr[node + 1];

    if (rs < re) {
        int s = g_col[rs];
        uint4 cur = *reinterpret_cast<const uint4*>(xlrh + (size_t)s * SR + base);
        for (int p = rs; p < re; p++) {
            int sn = (p + 1 < re) ? g_col[p + 1] : s;
            uint4 nxt = *reinterpret_cast<const uint4*>(xlrh + (size_t)sn * SR + base);

            float xlv[CPL];
            const __half2* cp = reinterpret_cast<const __half2*>(&cur);
#pragma unroll
            for (int j = 0; j < 4; j++) {
                float2 f = __half22float2(cp[j]);
                xlv[2 * j] = f.x; xlv[2 * j + 1] = f.y;
            }
            float partial = 0.f;
#pragma unroll
            for (int c = 0; c < CPL; c++) {
                float e = xlv[c] + xrv[c];
                e = (e >= 0.f) ? e : 0.2f * e;
                partial = fmaf(attv[c], e, partial);
            }
            partial += __shfl_xor_sync(0xffffffffu, partial, 1);
            partial += __shfl_xor_sync(0xffffffffu, partial, 2);
            partial += __shfl_xor_sync(0xffffffffu, partial, 4);
            partial += __shfl_xor_sync(0xffffffffu, partial, 8);

            float mnew = fmaxf(m, partial);
            float fac = __expf(m - mnew);
            float w = __expf(partial - mnew);
            ssum = ssum * fac + w;
#pragma unroll
            for (int c = 0; c < CPL; c++) acc[c] = fmaf(acc[c], fac, w * xlv[c]);
            m = mnew;
            cur = nxt;
        }
    }

    float inv = (ssum > 0.f) ? (1.f / ssum) : 0.f;
#pragma unroll
    for (int j = 0; j < CPL / 2; j++) {
        float v0 = fmaxf(fmaf(acc[2 * j], inv, bias[base + 2 * j]), 0.f);
        float v1 = fmaxf(fmaf(acc[2 * j + 1], inv, bias[base + 2 * j + 1]), 0.f);
        __half h0, l0, h1, l1;
        split1h(v0, h0, l0);
        split1h(v1, h1, l1);
        *reinterpret_cast<__half2*>(ohi + (size_t)node * 512 + base + 2 * j) = __halves2half2(h0, h1);
        *reinterpret_cast<__half2*>(olo + (size_t)node * 512 + base + 2 * j) = __halves2half2(l0, l1);
    }
}

// ---------------- launch ----------------
extern "C" void kernel_launch(void* const* d_in, const int* in_sizes, int n_in,
                              void* d_out, int out_size) {
    (void)in_sizes; (void)n_in; (void)out_size;
    const float* x     = (const float*)d_in[0];
    const int*   ei    = (const int*)  d_in[1];
    const float* Wl1   = (const float*)d_in[3];
    const float* bl1   = (const float*)d_in[4];
    const float* Wr1   = (const float*)d_in[5];
    const float* br1   = (const float*)d_in[6];
    const float* att1  = (const float*)d_in[7];
    const float* bias1 = (const float*)d_in[8];
    const float* Wl2   = (const float*)d_in[9];
    const float* bl2   = (const float*)d_in[10];
    const float* Wr2   = (const float*)d_in[11];
    const float* br2   = (const float*)d_in[12];
    const float* att2  = (const float*)d_in[13];
    const float* bias2 = (const float*)d_in[14];
    const float* Wlin  = (const float*)d_in[15];
    const float* blin  = (const float*)d_in[16];
    float* out = (float*)d_out;

    const int* src = ei;
    const int* dst = ei + NE;

    __half *xhi, *xlo, *h1h, *h2hi, *h2lo, *xlr1h, *xlr2h;
    __half *wt1h, *wt2h, *wtlh;
    float *cb1, *cb2;
    cudaGetSymbolAddress((void**)&xhi, g_xhi);
    cudaGetSymbolAddress((void**)&xlo, g_xlo);
    cudaGetSymbolAddress((void**)&h1h, g_h1h);
    cudaGetSymbolAddress((void**)&h2hi, g_h2hi);
    cudaGetSymbolAddress((void**)&h2lo, g_h2lo);
    cudaGetSymbolAddress((void**)&xlr1h, g_xlr1h);
    cudaGetSymbolAddress((void**)&xlr2h, g_xlr2h);
    cudaGetSymbolAddress((void**)&wt1h, g_wt1h);
    cudaGetSymbolAddress((void**)&wt2h, g_wt2h);
    cudaGetSymbolAddress((void**)&wtlh, g_wtlh);
    cudaGetSymbolAddress((void**)&cb1, g_cb1);
    cudaGetSymbolAddress((void**)&cb2, g_cb2);

    constexpr int SMEM_SPLIT128  = 2 * (2 * 64 * 40 + 128 * 40) * 2;  // 40960 B
    constexpr int SMEM_SINGLE128 = 2 * (1 * 64 * 40 + 128 * 40) * 2;  // 30720 B
    constexpr int SMEM_SPLIT64   = 2 * (2 * 64 * 40 + 64 * 40) * 2;   // 30720 B
    static cudaStream_t s_aux = nullptr;
    static cudaEvent_t e_fork = nullptr, e_csr = nullptr;
    if (!s_aux) {
        cudaFuncSetAttribute((const void*)gemm_f16<128, true, true>,  cudaFuncAttributeMaxDynamicSharedMemorySize, SMEM_SPLIT128);
        cudaFuncSetAttribute((const void*)gemm_f16<128, true, false>, cudaFuncAttributeMaxDynamicSharedMemorySize, SMEM_SINGLE128);
        cudaFuncSetAttribute((const void*)gemm_f16<64, false, true>,  cudaFuncAttributeMaxDynamicSharedMemorySize, SMEM_SPLIT64);
        cudaStreamCreateWithFlags(&s_aux, cudaStreamNonBlocking);
        cudaEventCreateWithFlags(&e_fork, cudaEventDisableTiming);
        cudaEventCreateWithFlags(&e_csr, cudaEventDisableTiming);
    }

    const int MB = (NN + 63) / 64;  // 313

    // #1: fused prep
    k_prep<<<(PREP_TOTAL + 255) / 256, 256>>>(x, Wl1, Wr1, Wl2, Wr2, Wlin, bl1, br1, bl2, br2);

    // fork CSR build onto side stream
    cudaEventRecord(e_fork, 0);
    cudaStreamWaitEvent(s_aux, e_fork, 0);
    k_hist<<<(NE + 255) / 256, 256, 0, s_aux>>>(dst);                 // #2
    k_scan<<<1, 1024, 0, s_aux>>>();                                  // #3

    // #4 (profiled slot): layer-1 GEMM (split A = x, fp16 out)
    gemm_f16<128, true, true><<<dim3(2, MB), 256, SMEM_SPLIT128>>>(xhi, xlo, wt1h, cb1, xlr1h, NN, 256, 128);

    k_scatter<<<(NE + 255) / 256, 256, 0, s_aux>>>(src, dst);         // #5
    cudaEventRecord(e_csr, s_aux);
    cudaStreamWaitEvent(0, e_csr, 0);

    k_agg1<<<(NN * 32 + 255) / 256, 256>>>(xlr1h, att1, bias1, h1h);
    // layer-2 GEMM: single-fp16 A (h1), 1 MMA per fragment
    gemm_f16<128, true, false><<<dim3(8, MB), 256, SMEM_SINGLE128>>>(h1h, h1h, wt2h, cb2, xlr2h, NN, 1024, 128);
    k_agg2<<<(NN * 2 * 32 + 255) / 256, 256>>>(xlr2h, att2, bias2, h2hi, h2lo);
    // output GEMM: keep split A (h2) for accuracy
    gemm_f16<64, false, true><<<dim3(1, MB), 256, SMEM_SPLIT64>>>(h2hi, h2lo, wtlh, blin, out, NN, 64, 512);
}

// round 15
// speedup vs baseline: 1.3210x; 1.0742x over previous
#include <cuda_runtime.h>
#include <cuda_fp16.h>
#include <cstdint>

#define NN 20000
#define NE 160000

// ---------------- scratch (device globals: allocation-free) ----------------
__device__ __half g_xh[NN * 128];
__device__ __half g_xlr1h[NN * 256];
__device__ __half g_h1h[NN * 128];
__device__ __half g_xlr2h[NN * 1024];
__device__ __half g_h2h[NN * 512];
__device__ __half g_wt1h[256 * 128];
__device__ __half g_wt2h[1024 * 128];
__device__ __half g_wtlh[64 * 512];
__device__ float g_cb1[256];
__device__ float g_cb2[1024];
__device__ int g_deg[NN];
__device__ int g_rowptr[NN + 1];
__device__ int g_cursor[NN];
__device__ int g_col[NE];

// ---------------- helpers ----------------
__device__ __forceinline__ uint32_t smem_u32(const void* p) {
    uint32_t a;
    asm("{ .reg .u64 t; cvta.to.shared.u64 t, %1; cvt.u32.u64 %0, t; }" : "=r"(a) : "l"(p));
    return a;
}
__device__ __forceinline__ void cp_async16(uint32_t dst, const void* src, bool pred) {
    int sz = pred ? 16 : 0;
    asm volatile("cp.async.cg.shared.global [%0], [%1], 16, %2;"
                 :: "r"(dst), "l"(src), "r"(sz) : "memory");
}
__device__ __forceinline__ void cp_commit() {
    asm volatile("cp.async.commit_group;" ::: "memory");
}
template <int W> __device__ __forceinline__ void cp_wait() {
    asm volatile("cp.async.wait_group %0;" :: "n"(W) : "memory");
}
__device__ __forceinline__ void mma_f16(float* c, const uint32_t* a, const uint32_t* b) {
    asm volatile("mma.sync.aligned.m16n8k16.row.col.f32.f16.f16.f32 "
                 "{%0,%1,%2,%3}, {%4,%5,%6,%7}, {%8,%9}, {%0,%1,%2,%3};"
                 : "+f"(c[0]), "+f"(c[1]), "+f"(c[2]), "+f"(c[3])
                 : "r"(a[0]), "r"(a[1]), "r"(a[2]), "r"(a[3]), "r"(b[0]), "r"(b[1]));
}
__device__ __forceinline__ void ldsm_x4(uint32_t* r, uint32_t addr) {
    asm volatile("ldmatrix.sync.aligned.m8n8.x4.shared.b16 {%0,%1,%2,%3}, [%4];"
                 : "=r"(r[0]), "=r"(r[1]), "=r"(r[2]), "=r"(r[3]) : "r"(addr));
}

// ---------------- fused prep: zero_deg + x convert + W transposes + bias ---
__global__ void k_prep(const float* __restrict__ x,
                       const float* __restrict__ Wl1, const float* __restrict__ Wr1,
                       const float* __restrict__ Wl2, const float* __restrict__ Wr2,
                       const float* __restrict__ Wlin,
                       const float* __restrict__ bl1, const float* __restrict__ br1,
                       const float* __restrict__ bl2, const float* __restrict__ br2) {
    const int S0 = NN;
    const int S1 = S0 + NN * 128;
    const int S2 = S1 + 16384;
    const int S3 = S2 + 16384;
    const int S4 = S3 + 65536;
    const int S5 = S4 + 65536;
    const int S6 = S5 + 32768;
    const int S7 = S6 + 1280;
    int i = blockIdx.x * blockDim.x + threadIdx.x;
    if (i < S0) {
        g_deg[i] = 0;
    } else if (i < S1) {
        int j = i - S0;
        g_xh[j] = __float2half_rn(x[j]);
    } else if (i < S2) {
        int j = i - S1, k = j >> 7, n = j & 127;
        g_wt1h[n * 128 + k] = __float2half_rn(Wl1[j]);
    } else if (i < S3) {
        int j = i - S2, k = j >> 7, n = j & 127;
        g_wt1h[128 * 128 + n * 128 + k] = __float2half_rn(Wr1[j]);
    } else if (i < S4) {
        int j = i - S3, k = j >> 9, n = j & 511;
        g_wt2h[n * 128 + k] = __float2half_rn(Wl2[j]);
    } else if (i < S5) {
        int j = i - S4, k = j >> 9, n = j & 511;
        g_wt2h[512 * 128 + n * 128 + k] = __float2half_rn(Wr2[j]);
    } else if (i < S6) {
        int j = i - S5, k = j >> 6, n = j & 63;
        g_wtlh[n * 512 + k] = __float2half_rn(Wlin[j]);
    } else if (i < S7) {
        int j = i - S6;
        if (j < 256) g_cb1[j] = (j < 128) ? bl1[j] : br1[j - 128];
        else {
            int b = j - 256;
            g_cb2[b] = (b < 512) ? bl2[b] : br2[b - 512];
        }
    }
}
#define PREP_TOTAL (NN + NN * 128 + 16384 * 2 + 65536 * 2 + 32768 + 1280)

// ---------------- CSR build (counting sort by dst) ----------------
__global__ void k_hist(const int* __restrict__ dst) {
    int e = blockIdx.x * blockDim.x + threadIdx.x;
    if (e < NE) atomicAdd(&g_deg[dst[e]], 1);
}
__global__ void k_scan() {
    __shared__ int s[1024];
    const int CH = (NN + 1023) / 1024;
    int t = threadIdx.x;
    int start = t * CH;
    int end = start + CH < NN ? start + CH : NN;
    int sum = 0;
    for (int i = start; i < end; i++) sum += g_deg[i];
    s[t] = sum;
    __syncthreads();
    for (int off = 1; off < 1024; off <<= 1) {
        int v = (t >= off) ? s[t - off] : 0;
        __syncthreads();
        s[t] += v;
        __syncthreads();
    }
    int run = (t == 0) ? 0 : s[t - 1];
    for (int i = start; i < end; i++) {
        g_rowptr[i] = run;
        g_cursor[i] = run;
        run += g_deg[i];
    }
    if (t == 1023) g_rowptr[NN] = s[1023];
}
__global__ void k_scatter(const int* __restrict__ src, const int* __restrict__ dst) {
    int e = blockIdx.x * blockDim.x + threadIdx.x;
    if (e < NE) {
        int d = dst[e];
        int pos = atomicAdd(&g_cursor[d], 1);
        g_col[pos] = src[e];
    }
}

// ---------------- pipelined fp16 GEMM (single-A, R9 2-stage) --------------
// C = A[M,K] @ B[N,K]^T + bias, fp32 accumulate. HOUT: fp16 C.
template <int BN, bool HOUT>
__global__ void __launch_bounds__(256, 3)
gemm_f16(const __half* __restrict__ Ah, const __half* __restrict__ Bh,
         const float* __restrict__ bias, void* __restrict__ Cv,
         int M, int N, int K) {
    constexpr int BM = 64;
    constexpr int BK = 32;
    constexpr int STR = 40;
    constexpr int ASZ = BM * STR;
    constexpr int BSZ = BN * STR;
    constexpr int STAGE = ASZ + BSZ;
    constexpr int NT = BN / 32;
    extern __shared__ __half sm[];

    const int tid = threadIdx.x;
    const int wid = tid >> 5;
    const int lane = tid & 31;
    const int wm = wid & 1;
    const int wn = wid >> 1;
    const int gid = lane >> 2;
    const int tig = lane & 3;
    const int m0 = blockIdx.y * BM;
    const int n0 = blockIdx.x * BN;
    const int nk = K / BK;

    const int a_row = wm * 32 + (lane & 7) + ((lane >> 3) & 1) * 8;
    const int a_koff = (lane & 16) >> 1;
    const int b_row = wn * (NT * 8) + (lane & 7) + ((lane & 16) >> 1);
    const int b_koff = lane & 8;

    float c[2][NT][4];
#pragma unroll
    for (int mt = 0; mt < 2; mt++)
#pragma unroll
        for (int nt = 0; nt < NT; nt++)
#pragma unroll
            for (int r = 0; r < 4; r++) c[mt][nt][r] = 0.f;

    auto load_stage = [&](int kc, int s) {
        const int k0 = kc * BK;
        __half* base = sm + s * STAGE;
        {
            int row = tid >> 2, ch = tid & 3;
            int gm = m0 + row;
            bool p = gm < M;
            int gmc = p ? gm : (M - 1);
            size_t goff = (size_t)gmc * K + k0 + ch * 8;
            uint32_t d = smem_u32(base + row * STR + ch * 8);
            cp_async16(d, Ah + goff, p);
        }
#pragma unroll
        for (int j = 0; j < BN / 64; j++) {
            int i = tid + j * 256;
            int row = i >> 2, ch = i & 3;
            size_t goff = (size_t)(n0 + row) * K + k0 + ch * 8;
            uint32_t d = smem_u32(base + ASZ + row * STR + ch * 8);
            cp_async16(d, Bh + goff, true);
        }
    };

    load_stage(0, 0);
    cp_commit();

    for (int kc = 0; kc < nk; kc++) {
        const int s = kc & 1;
        if (kc + 1 < nk) {
            load_stage(kc + 1, s ^ 1);
            cp_commit();
            cp_wait<1>();
        } else {
            cp_wait<0>();
        }
        __syncthreads();

        const uint32_t stg = smem_u32(sm + s * STAGE);
        const uint32_t ah_base = stg + (a_row * STR + a_koff) * 2;
        const uint32_t bh_base = stg + ASZ * 2 + (b_row * STR + b_koff) * 2;

#pragma unroll
        for (int kb = 0; kb < BK; kb += 16) {
            uint32_t bfh[NT][2];
#pragma unroll
            for (int p = 0; p < NT / 2; p++) {
                uint32_t off = (p * 16 * STR + kb) * 2;
                ldsm_x4(&bfh[2 * p][0], bh_base + off);
            }
#pragma unroll
            for (int mt = 0; mt < 2; mt++) {
                uint32_t afh[4];
                uint32_t off = (mt * 16 * STR + kb) * 2;
                ldsm_x4(afh, ah_base + off);
#pragma unroll
                for (int nt = 0; nt < NT; nt++)
                    mma_f16(c[mt][nt], afh, bfh[nt]);
            }
        }
        __syncthreads();
    }

#pragma unroll
    for (int mt = 0; mt < 2; mt++) {
        int r0 = m0 + wm * 32 + mt * 16 + gid;
#pragma unroll
        for (int nt = 0; nt < NT; nt++) {
            int col = n0 + wn * (NT * 8) + nt * 8 + tig * 2;
            float b0 = bias[col], b1 = bias[col + 1];
            if (HOUT) {
                __half* Ch = (__half*)Cv;
                if (r0 < M)
                    *reinterpret_cast<__half2*>(Ch + (size_t)r0 * N + col) =
                        __floats2half2_rn(c[mt][nt][0] + b0, c[mt][nt][1] + b1);
                if (r0 + 8 < M)
                    *reinterpret_cast<__half2*>(Ch + (size_t)(r0 + 8) * N + col) =
                        __floats2half2_rn(c[mt][nt][2] + b0, c[mt][nt][3] + b1);
            } else {
                float* Cf = (float*)Cv;
                if (r0 < M) {
                    float2 v0 = make_float2(c[mt][nt][0] + b0, c[mt][nt][1] + b1);
                    *reinterpret_cast<float2*>(Cf + (size_t)r0 * N + col) = v0;
                }
                if (r0 + 8 < M) {
                    float2 v1 = make_float2(c[mt][nt][2] + b0, c[mt][nt][3] + b1);
                    *reinterpret_cast<float2*>(Cf + (size_t)(r0 + 8) * N + col) = v1;
                }
            }
        }
    }
}

// ---------------- layer-1 agg (fp16 in, fp16 h1 out) -----------------------
__global__ void __launch_bounds__(256, 3)
k_agg1(const __half* __restrict__ xlrh,
       const float* __restrict__ att, const float* __restrict__ bias,
       __half* __restrict__ oh) {
    constexpr int D = 128, SR = 256, XO = 128;
    constexpr int CPL = 4;

    int warp = (blockIdx.x * blockDim.x + threadIdx.x) >> 5;
    int lane = threadIdx.x & 31;
    if (warp >= NN) return;
    const int node = warp;
    const int base = lane * CPL;

    float attv[CPL], xrv[CPL];
    {
        float4 a4 = *reinterpret_cast<const float4*>(att + base);
        attv[0] = a4.x; attv[1] = a4.y; attv[2] = a4.z; attv[3] = a4.w;
        uint2 r = *reinterpret_cast<const uint2*>(xlrh + (size_t)node * SR + XO + base);
        const __half2* rp = reinterpret_cast<const __half2*>(&r);
        float2 f0 = __half22float2(rp[0]);
        float2 f1 = __half22float2(rp[1]);
        xrv[0] = f0.x; xrv[1] = f0.y; xrv[2] = f1.x; xrv[3] = f1.y;
    }

    float m = -3.402823466e38f;
    float ssum = 0.f;
    float acc[CPL];
#pragma unroll
    for (int c = 0; c < CPL; c++) acc[c] = 0.f;

    const int rs = g_rowptr[node];
    const int re = g_rowptr[node + 1];

    if (rs < re) {
        int s = g_col[rs];
        uint2 cur = *reinterpret_cast<const uint2*>(xlrh + (size_t)s * SR + base);
        for (int p = rs; p < re; p++) {
            int sn = (p + 1 < re) ? g_col[p + 1] : s;
            uint2 nxt = *reinterpret_cast<const uint2*>(xlrh + (size_t)sn * SR + base);

            float xlv[CPL];
            const __half2* cp = reinterpret_cast<const __half2*>(&cur);
            float2 f0 = __half22float2(cp[0]);
            float2 f1 = __half22float2(cp[1]);
            xlv[0] = f0.x; xlv[1] = f0.y; xlv[2] = f1.x; xlv[3] = f1.y;

            float partial = 0.f;
#pragma unroll
            for (int c = 0; c < CPL; c++) {
                float e = xlv[c] + xrv[c];
                e = (e >= 0.f) ? e : 0.2f * e;
                partial = fmaf(attv[c], e, partial);
            }
            partial += __shfl_xor_sync(0xffffffffu, partial, 1);
            partial += __shfl_xor_sync(0xffffffffu, partial, 2);
            partial += __shfl_xor_sync(0xffffffffu, partial, 4);

            float mnew = fmaxf(m, partial);
            float fac = __expf(m - mnew);
            float w = __expf(partial - mnew);
            ssum = ssum * fac + w;
#pragma unroll
            for (int c = 0; c < CPL; c++) acc[c] = fmaf(acc[c], fac, w * xlv[c]);
            m = mnew;
            cur = nxt;
        }
    }

    float inv = (ssum > 0.f) ? (1.f / ssum) : 0.f;
#pragma unroll
    for (int j = 0; j < CPL / 2; j++) {
        float v0 = fmaxf(fmaf(acc[2 * j], inv, bias[base + 2 * j]), 0.f);
        float v1 = fmaxf(fmaf(acc[2 * j + 1], inv, bias[base + 2 * j + 1]), 0.f);
        *reinterpret_cast<__half2*>(oh + (size_t)node * D + base + 2 * j) = __floats2half2_rn(v0, v1);
    }
}

// ---------------- layer-2 agg (fp16 in, fp16 h2 out) -----------------------
__global__ void __launch_bounds__(256, 3)
k_agg2(const __half* __restrict__ xlrh,
       const float* __restrict__ att, const float* __restrict__ bias,
       __half* __restrict__ oh) {
    constexpr int SR = 1024, XO = 512;
    constexpr int CPL = 8;

    int gw = (blockIdx.x * blockDim.x + threadIdx.x) >> 5;
    int lane = threadIdx.x & 31;
    int node = gw >> 1;
    int part = gw & 1;
    if (node >= NN) return;
    const int base = part * 256 + lane * CPL;

    float attv[CPL], xrv[CPL];
    {
        float4 a0 = *reinterpret_cast<const float4*>(att + base);
        float4 a1 = *reinterpret_cast<const float4*>(att + base + 4);
        attv[0] = a0.x; attv[1] = a0.y; attv[2] = a0.z; attv[3] = a0.w;
        attv[4] = a1.x; attv[5] = a1.y; attv[6] = a1.z; attv[7] = a1.w;
        uint4 r = *reinterpret_cast<const uint4*>(xlrh + (size_t)node * SR + XO + base);
        const __half2* rp = reinterpret_cast<const __half2*>(&r);
#pragma unroll
        for (int j = 0; j < 4; j++) {
            float2 f = __half22float2(rp[j]);
            xrv[2 * j] = f.x; xrv[2 * j + 1] = f.y;
        }
    }

    float m = -3.402823466e38f;
    float ssum = 0.f;
    float acc[CPL];
#pragma unroll
    for (int c = 0; c < CPL; c++) acc[c] = 0.f;

    const int rs = g_rowptr[node];
    const int re = g_rowptr[node + 1];

    if (rs < re) {
        int s = g_col[rs];
        uint4 cur = *reinterpret_cast<const uint4*>(xlrh + (size_t)s * SR + base);
        for (int p = rs; p < re; p++) {
            int sn = (p + 1 < re) ? g_col[p + 1] : s;
            uint4 nxt = *reinterpret_cast<const uint4*>(xlrh + (size_t)sn * SR + base);

            float xlv[CPL];
            const __half2* cp = reinterpret_cast<const __half2*>(&cur);
#pragma unroll
            for (int j = 0; j < 4; j++) {
                float2 f = __half22float2(cp[j]);
                xlv[2 * j] = f.x; xlv[2 * j + 1] = f.y;
            }
            float partial = 0.f;
#pragma unroll
            for (int c = 0; c < CPL; c++) {
                float e = xlv[c] + xrv[c];
                e = (e >= 0.f) ? e : 0.2f * e;
                partial = fmaf(attv[c], e, partial);
            }
            partial += __shfl_xor_sync(0xffffffffu, partial, 1);
            partial += __shfl_xor_sync(0xffffffffu, partial, 2);
            partial += __shfl_xor_sync(0xffffffffu, partial, 4);
            partial += __shfl_xor_sync(0xffffffffu, partial, 8);

            float mnew = fmaxf(m, partial);
            float fac = __expf(m - mnew);
            float w = __expf(partial - mnew);
            ssum = ssum * fac + w;
#pragma unroll
            for (int c = 0; c < CPL; c++) acc[c] = fmaf(acc[c], fac, w * xlv[c]);
            m = mnew;
            cur = nxt;
        }
    }

    float inv = (ssum > 0.f) ? (1.f / ssum) : 0.f;
#pragma unroll
    for (int j = 0; j < CPL / 2; j++) {
        float v0 = fmaxf(fmaf(acc[2 * j], inv, bias[base + 2 * j]), 0.f);
        float v1 = fmaxf(fmaf(acc[2 * j + 1], inv, bias[base + 2 * j + 1]), 0.f);
        *reinterpret_cast<__half2*>(oh + (size_t)node * 512 + base + 2 * j) = __floats2half2_rn(v0, v1);
    }
}

// ---------------- launch ----------------
extern "C" void kernel_launch(void* const* d_in, const int* in_sizes, int n_in,
                              void* d_out, int out_size) {
    (void)in_sizes; (void)n_in; (void)out_size;
    const float* x     = (const float*)d_in[0];
    const int*   ei    = (const int*)  d_in[1];
    const float* Wl1   = (const float*)d_in[3];
    const float* bl1   = (const float*)d_in[4];
    const float* Wr1   = (const float*)d_in[5];
    const float* br1   = (const float*)d_in[6];
    const float* att1  = (const float*)d_in[7];
    const float* bias1 = (const float*)d_in[8];
    const float* Wl2   = (const float*)d_in[9];
    const float* bl2   = (const float*)d_in[10];
    const float* Wr2   = (const float*)d_in[11];
    const float* br2   = (const float*)d_in[12];
    const float* att2  = (const float*)d_in[13];
    const float* bias2 = (const float*)d_in[14];
    const float* Wlin  = (const float*)d_in[15];
    const float* blin  = (const float*)d_in[16];
    float* out = (float*)d_out;

    const int* src = ei;
    const int* dst = ei + NE;

    __half *xh, *h1h, *h2h, *xlr1h, *xlr2h;
    __half *wt1h, *wt2h, *wtlh;
    float *cb1, *cb2;
    cudaGetSymbolAddress((void**)&xh, g_xh);
    cudaGetSymbolAddress((void**)&h1h, g_h1h);
    cudaGetSymbolAddress((void**)&h2h, g_h2h);
    cudaGetSymbolAddress((void**)&xlr1h, g_xlr1h);
    cudaGetSymbolAddress((void**)&xlr2h, g_xlr2h);
    cudaGetSymbolAddress((void**)&wt1h, g_wt1h);
    cudaGetSymbolAddress((void**)&wt2h, g_wt2h);
    cudaGetSymbolAddress((void**)&wtlh, g_wtlh);
    cudaGetSymbolAddress((void**)&cb1, g_cb1);
    cudaGetSymbolAddress((void**)&cb2, g_cb2);

    constexpr int SMEM128 = 2 * (64 * 40 + 128 * 40) * 2;  // 30720 B
    constexpr int SMEM64  = 2 * (64 * 40 + 64 * 40) * 2;   // 20480 B
    static cudaStream_t s_aux = nullptr;
    static cudaEvent_t e_fork = nullptr, e_csr = nullptr;
    if (!s_aux) {
        cudaFuncSetAttribute((const void*)gemm_f16<128, true>,  cudaFuncAttributeMaxDynamicSharedMemorySize, SMEM128);
        cudaFuncSetAttribute((const void*)gemm_f16<64, false>,  cudaFuncAttributeMaxDynamicSharedMemorySize, SMEM64);
        cudaStreamCreateWithFlags(&s_aux, cudaStreamNonBlocking);
        cudaEventCreateWithFlags(&e_fork, cudaEventDisableTiming);
        cudaEventCreateWithFlags(&e_csr, cudaEventDisableTiming);
    }

    const int MB = (NN + 63) / 64;  // 313

    // #1: fused prep
    k_prep<<<(PREP_TOTAL + 255) / 256, 256>>>(x, Wl1, Wr1, Wl2, Wr2, Wlin, bl1, br1, bl2, br2);

    // fork CSR build onto side stream
    cudaEventRecord(e_fork, 0);
    cudaStreamWaitEvent(s_aux, e_fork, 0);
    k_hist<<<(NE + 255) / 256, 256, 0, s_aux>>>(dst);                 // #2
    k_scan<<<1, 1024, 0, s_aux>>>();                                  // #3

    // #4 (profiled slot): layer-1 GEMM (single-A fp16)
    gemm_f16<128, true><<<dim3(2, MB), 256, SMEM128>>>(xh, wt1h, cb1, xlr1h, NN, 256, 128);

    k_scatter<<<(NE + 255) / 256, 256, 0, s_aux>>>(src, dst);         // #5
    cudaEventRecord(e_csr, s_aux);
    cudaStreamWaitEvent(0, e_csr, 0);

    k_agg1<<<(NN * 32 + 255) / 256, 256>>>(xlr1h, att1, bias1, h1h);
    gemm_f16<128, true><<<dim3(8, MB), 256, SMEM128>>>(h1h, wt2h, cb2, xlr2h, NN, 1024, 128);
    k_agg2<<<(NN * 2 * 32 + 255) / 256, 256>>>(xlr2h, att2, bias2, h2h);
    gemm_f16<64, false><<<dim3(1, MB), 256, SMEM64>>>(h2h, wtlh, blin, out, NN, 64, 512);
}